// round 1
// baseline (speedup 1.0000x reference)
#include <cuda_runtime.h>
#include <cuda_bf16.h>
#include <math.h>

// ---------------------------------------------------------------------------
// Problem constants
// ---------------------------------------------------------------------------
#define NNODES   50000
#define NEDGES   800000
#define IN_DIM   128
#define HIDDEN   64
#define HEADS    4
#define NGRAPHS  256
#define HC1      256   // HEADS*HIDDEN
#define NEG_SLOPE 0.2f

// ---------------------------------------------------------------------------
// Device scratch (static globals: no allocation allowed)
// ---------------------------------------------------------------------------
__device__ float g_hw[(size_t)NNODES * HC1];    // h = X @ W^T  (current layer)
__device__ float g_feat[(size_t)NNODES * HC1];  // aggregated+elu output -> next layer input
__device__ float g_alo[NNODES * HEADS];
__device__ float g_ahi[NNODES * HEADS];
__device__ int   g_off[NNODES + 1];             // CSR offsets by dst
__device__ int   g_fill[NNODES];                // scatter cursors
__device__ int   g_csr[NEDGES];                 // src per CSR slot
__device__ float g_pool[NGRAPHS * HIDDEN];
__device__ float g_cnt[NGRAPHS];

// ---------------------------------------------------------------------------
// Small utility kernels
// ---------------------------------------------------------------------------
__global__ void k_zero_csr() {
    int i = blockIdx.x * blockDim.x + threadIdx.x;
    if (i <= NNODES) g_off[i] = 0;
    if (i < NGRAPHS * HIDDEN) g_pool[i] = 0.f;
    if (i < NGRAPHS) g_cnt[i] = 0.f;
}

__global__ void k_hist(const int* __restrict__ dst) {
    int e = blockIdx.x * blockDim.x + threadIdx.x;
    if (e < NEDGES) atomicAdd(&g_off[dst[e] + 1], 1);
}

// single-block inclusive scan over g_off[1..N]
__global__ void k_scan() {
    __shared__ int s[1024];
    __shared__ int carry;
    int t = threadIdx.x;
    if (t == 0) carry = 0;
    __syncthreads();
    for (int base = 0; base < NNODES; base += 1024) {
        int i = base + t;
        int v = (i < NNODES) ? g_off[i + 1] : 0;
        s[t] = v; __syncthreads();
        #pragma unroll
        for (int off = 1; off < 1024; off <<= 1) {
            int add = (t >= off) ? s[t - off] : 0;
            __syncthreads();
            s[t] += add;
            __syncthreads();
        }
        if (i < NNODES) g_off[i + 1] = carry + s[t];
        __syncthreads();
        if (t == 0) carry += s[1023];
        __syncthreads();
    }
}

__global__ void k_fill_init() {
    int i = blockIdx.x * blockDim.x + threadIdx.x;
    if (i < NNODES) g_fill[i] = g_off[i];
}

__global__ void k_scatter(const int* __restrict__ src, const int* __restrict__ dst) {
    int e = blockIdx.x * blockDim.x + threadIdx.x;
    if (e < NEDGES) {
        int p = atomicAdd(&g_fill[dst[e]], 1);
        g_csr[p] = src[e];
    }
}

// ---------------------------------------------------------------------------
// GEMM: C[M,Nn] = A[M,K] @ B[Nn,K]^T   (both K-contiguous, "NT")
// 64x64 tile, BK=16, 256 threads, 4x4 per thread
// ---------------------------------------------------------------------------
__global__ void k_gemm_nt(const float* __restrict__ A, const float* __restrict__ B,
                          float* __restrict__ C, int M, int Nn, int K) {
    const int BM = 64, BN = 64, BK = 16;
    __shared__ float sA[BK][BM];
    __shared__ float sB[BK][BN];
    int t  = threadIdx.x;
    int m0 = blockIdx.y * BM, n0 = blockIdx.x * BN;
    int tx = t & 15, ty = t >> 4;
    float acc[4][4] = {};
    for (int k0 = 0; k0 < K; k0 += BK) {
        #pragma unroll
        for (int i = 0; i < 4; i++) {
            int idx = t + i * 256;
            int r = idx / BK, c = idx % BK;
            int gm = m0 + r;
            sA[c][r] = (gm < M) ? A[(size_t)gm * K + k0 + c] : 0.f;
            int gn = n0 + r;
            sB[c][r] = (gn < Nn) ? B[(size_t)gn * K + k0 + c] : 0.f;
        }
        __syncthreads();
        #pragma unroll
        for (int kk = 0; kk < BK; kk++) {
            float ra[4], rb[4];
            #pragma unroll
            for (int i = 0; i < 4; i++) ra[i] = sA[kk][ty * 4 + i];
            #pragma unroll
            for (int i = 0; i < 4; i++) rb[i] = sB[kk][tx * 4 + i];
            #pragma unroll
            for (int i = 0; i < 4; i++)
                #pragma unroll
                for (int j = 0; j < 4; j++)
                    acc[i][j] += ra[i] * rb[j];
        }
        __syncthreads();
    }
    #pragma unroll
    for (int i = 0; i < 4; i++) {
        int gm = m0 + ty * 4 + i;
        if (gm >= M) continue;
        #pragma unroll
        for (int j = 0; j < 4; j++) {
            int gn = n0 + tx * 4 + j;
            if (gn < Nn) C[(size_t)gm * Nn + gn] = acc[i][j];
        }
    }
}

// ---------------------------------------------------------------------------
// Attention coefficients: alo[n,h] = <h[n,h,:], a_src[h,:]>, ahi likewise
// One warp per node.
// ---------------------------------------------------------------------------
template <int H, int C>
__global__ void k_attn_coef(const float* __restrict__ h,
                            const float* __restrict__ a_src,
                            const float* __restrict__ a_dst,
                            float* __restrict__ alo, float* __restrict__ ahi) {
    const int HCn = H * C;
    const int FPL = HCn / 32;     // features per lane
    const int LPH = 32 / H;       // lanes per head
    int warp = (blockIdx.x * blockDim.x + threadIdx.x) >> 5;
    int lane = threadIdx.x & 31;
    if (warp >= NNODES) return;
    const float* hr = h + (size_t)warp * HCn + lane * FPL;
    float s_lo = 0.f, s_hi = 0.f;
    #pragma unroll
    for (int i = 0; i < FPL; i++) {
        float v = hr[i];
        s_lo += v * a_src[lane * FPL + i];
        s_hi += v * a_dst[lane * FPL + i];
    }
    #pragma unroll
    for (int off = LPH / 2; off > 0; off >>= 1) {
        s_lo += __shfl_down_sync(0xffffffffu, s_lo, off);
        s_hi += __shfl_down_sync(0xffffffffu, s_hi, off);
    }
    if ((lane % LPH) == 0) {
        int hh = lane / LPH;
        alo[warp * H + hh] = s_lo;
        ahi[warp * H + hh] = s_hi;
    }
}

// ---------------------------------------------------------------------------
// Aggregation with segment softmax. One warp per dst node.
//   pass1: max_e over edges (incl. self loop)
//   pass2: sum exp(e - m)
//   pass3: out = sum alpha * h[src], + bias, elu
// ---------------------------------------------------------------------------
__device__ __forceinline__ float lrelu(float x) { return x > 0.f ? x : NEG_SLOPE * x; }

template <int H, int C>
__global__ void k_aggregate(const float* __restrict__ hw,
                            const float* __restrict__ alo,
                            const float* __restrict__ ahi,
                            const float* __restrict__ bias,
                            float* __restrict__ out) {
    const int HCn = H * C;
    const int FPL = HCn / 32;
    const int LPH = 32 / H;
    int warp = (blockIdx.x * blockDim.x + threadIdx.x) >> 5;
    int lane = threadIdx.x & 31;
    if (warp >= NNODES) return;
    int n   = warp;
    int beg = g_off[n], deg = g_off[n + 1] - beg;

    float ahin[H];
    #pragma unroll
    for (int hh = 0; hh < H; hh++) ahin[hh] = ahi[n * H + hh];

    // pass 1: max
    float mx[H];
    #pragma unroll
    for (int hh = 0; hh < H; hh++) mx[hh] = -1e30f;
    for (int j = lane; j <= deg; j += 32) {
        int src = (j < deg) ? g_csr[beg + j] : n;
        #pragma unroll
        for (int hh = 0; hh < H; hh++) {
            float e = lrelu(alo[src * H + hh] + ahin[hh]);
            mx[hh] = fmaxf(mx[hh], e);
        }
    }
    #pragma unroll
    for (int off = 16; off > 0; off >>= 1)
        #pragma unroll
        for (int hh = 0; hh < H; hh++)
            mx[hh] = fmaxf(mx[hh], __shfl_xor_sync(0xffffffffu, mx[hh], off));

    // pass 2: denom
    float den[H];
    #pragma unroll
    for (int hh = 0; hh < H; hh++) den[hh] = 0.f;
    for (int j = lane; j <= deg; j += 32) {
        int src = (j < deg) ? g_csr[beg + j] : n;
        #pragma unroll
        for (int hh = 0; hh < H; hh++) {
            float e = lrelu(alo[src * H + hh] + ahin[hh]);
            den[hh] += __expf(e - mx[hh]);
        }
    }
    #pragma unroll
    for (int off = 16; off > 0; off >>= 1)
        #pragma unroll
        for (int hh = 0; hh < H; hh++)
            den[hh] += __shfl_xor_sync(0xffffffffu, den[hh], off);

    // per-lane head constants
    int hh_l = lane / LPH;
    float my_m = 0.f, my_d = 0.f, my_a = 0.f;
    #pragma unroll
    for (int hh = 0; hh < H; hh++)
        if (hh == hh_l) { my_m = mx[hh]; my_d = den[hh]; my_a = ahin[hh]; }
    float inv_d = 1.f / (my_d + 1e-16f);

    // pass 3: weighted gather
    float acc[FPL];
    #pragma unroll
    for (int i = 0; i < FPL; i++) acc[i] = 0.f;
    for (int j = 0; j <= deg; j++) {
        int src = (j < deg) ? g_csr[beg + j] : n;   // broadcast across warp
        float e = lrelu(alo[src * H + hh_l] + my_a);
        float w = __expf(e - my_m) * inv_d;
        const float* hp = hw + (size_t)src * HCn + lane * FPL;
        if (FPL == 8) {
            float4 v0 = *(const float4*)(hp);
            float4 v1 = *(const float4*)(hp + 4);
            acc[0] += w * v0.x; acc[1] += w * v0.y; acc[2] += w * v0.z; acc[3] += w * v0.w;
            acc[4] += w * v1.x; acc[5] += w * v1.y; acc[6] += w * v1.z; acc[7] += w * v1.w;
        } else {
            float2 v0 = *(const float2*)(hp);
            acc[0] += w * v0.x;
            if (FPL > 1) acc[1] += w * v0.y;
        }
    }
    // bias + elu, write
    #pragma unroll
    for (int i = 0; i < FPL; i++) {
        float v = acc[i] + bias[lane * FPL + i];
        v = (v > 0.f) ? v : (expm1f(v));
        out[(size_t)n * HCn + lane * FPL + i] = v;
    }
}

// ---------------------------------------------------------------------------
// Global mean pool (atomic accumulate)
// ---------------------------------------------------------------------------
__global__ void k_pool(const float* __restrict__ h3, const int* __restrict__ batch) {
    int warp = (blockIdx.x * blockDim.x + threadIdx.x) >> 5;
    int lane = threadIdx.x & 31;
    if (warp >= NNODES) return;
    int b = batch[warp];
    atomicAdd(&g_pool[b * HIDDEN + lane],      h3[(size_t)warp * HIDDEN + lane]);
    atomicAdd(&g_pool[b * HIDDEN + lane + 32], h3[(size_t)warp * HIDDEN + lane + 32]);
    if (lane == 0) atomicAdd(&g_cnt[b], 1.f);
}

// ---------------------------------------------------------------------------
// Heads MLP: one warp per graph; both cls and reg heads
// ---------------------------------------------------------------------------
__global__ void k_mlp(const float* __restrict__ Wc1, const float* __restrict__ bc1,
                      const float* __restrict__ Wc2, const float* __restrict__ bc2,
                      const float* __restrict__ Wr1, const float* __restrict__ br1,
                      const float* __restrict__ Wr2, const float* __restrict__ br2,
                      float* __restrict__ out) {
    int warp = (blockIdx.x * blockDim.x + threadIdx.x) >> 5;
    int lane = threadIdx.x & 31;
    if (warp >= NGRAPHS) return;
    float inv_cnt = 1.f / fmaxf(g_cnt[warp], 1.f);

    // graph feature gv[c] read on the fly (broadcast within warp)
    const float* gp = &g_pool[warp * HIDDEN];

    // cls head
    {
        float h0 = bc1[lane], h1 = bc1[lane + 32];
        for (int c = 0; c < HIDDEN; c++) {
            float gc = gp[c] * inv_cnt;
            h0 += Wc1[lane * HIDDEN + c] * gc;
            h1 += Wc1[(lane + 32) * HIDDEN + c] * gc;
        }
        h0 = fmaxf(h0, 0.f); h1 = fmaxf(h1, 0.f);
        float s = Wc2[lane] * h0 + Wc2[lane + 32] * h1;
        #pragma unroll
        for (int off = 16; off > 0; off >>= 1) s += __shfl_xor_sync(0xffffffffu, s, off);
        if (lane == 0) out[warp] = s + bc2[0];
    }
    // reg head
    {
        float h0 = br1[lane], h1 = br1[lane + 32];
        for (int c = 0; c < HIDDEN; c++) {
            float gc = gp[c] * inv_cnt;
            h0 += Wr1[lane * HIDDEN + c] * gc;
            h1 += Wr1[(lane + 32) * HIDDEN + c] * gc;
        }
        h0 = fmaxf(h0, 0.f); h1 = fmaxf(h1, 0.f);
        float s = Wr2[lane] * h0 + Wr2[lane + 32] * h1;
        #pragma unroll
        for (int off = 16; off > 0; off >>= 1) s += __shfl_xor_sync(0xffffffffu, s, off);
        if (lane == 0) out[NGRAPHS + warp] = s + br2[0];
    }
}

// ---------------------------------------------------------------------------
// Launch
// ---------------------------------------------------------------------------
extern "C" void kernel_launch(void* const* d_in, const int* in_sizes, int n_in,
                              void* d_out, int out_size) {
    const float* x     = (const float*)d_in[0];
    const int*   ei    = (const int*)d_in[1];
    const int*   batch = (const int*)d_in[2];
    const float* W1  = (const float*)d_in[3];
    const float* as1 = (const float*)d_in[4];
    const float* ad1 = (const float*)d_in[5];
    const float* b1  = (const float*)d_in[6];
    const float* W2  = (const float*)d_in[7];
    const float* as2 = (const float*)d_in[8];
    const float* ad2 = (const float*)d_in[9];
    const float* b2  = (const float*)d_in[10];
    const float* W3  = (const float*)d_in[11];
    const float* as3 = (const float*)d_in[12];
    const float* ad3 = (const float*)d_in[13];
    const float* b3  = (const float*)d_in[14];
    const float* Wc1 = (const float*)d_in[15];
    const float* bc1 = (const float*)d_in[16];
    const float* Wc2 = (const float*)d_in[17];
    const float* bc2 = (const float*)d_in[18];
    const float* Wr1 = (const float*)d_in[19];
    const float* br1 = (const float*)d_in[20];
    const float* Wr2 = (const float*)d_in[21];
    const float* br2 = (const float*)d_in[22];
    float* out = (float*)d_out;

    const int* srcp = ei;
    const int* dstp = ei + NEDGES;

    // ------- CSR build (by dst) + zero pools -------
    k_zero_csr<<<(NNODES + 256) / 256, 256>>>();
    k_hist<<<(NEDGES + 255) / 256, 256>>>(dstp);
    k_scan<<<1, 1024>>>();
    k_fill_init<<<(NNODES + 255) / 256, 256>>>();
    k_scatter<<<(NEDGES + 255) / 256, 256>>>(srcp, dstp);

    float* hw_p   = nullptr; cudaGetSymbolAddress((void**)&hw_p,   g_hw);
    float* feat_p = nullptr; cudaGetSymbolAddress((void**)&feat_p, g_feat);
    float* alo_p  = nullptr; cudaGetSymbolAddress((void**)&alo_p,  g_alo);
    float* ahi_p  = nullptr; cudaGetSymbolAddress((void**)&ahi_p,  g_ahi);

    dim3 gemm_blk(256);
    const int warps_grid = (NNODES * 32 + 255) / 256;

    // ------- Layer 1: x[50000,128] @ W1^T -> hw[50000,256] -------
    {
        dim3 grid(HC1 / 64, (NNODES + 63) / 64);
        k_gemm_nt<<<grid, gemm_blk>>>(x, W1, hw_p, NNODES, HC1, IN_DIM);
        k_attn_coef<HEADS, HIDDEN><<<warps_grid, 256>>>(hw_p, as1, ad1, alo_p, ahi_p);
        k_aggregate<HEADS, HIDDEN><<<warps_grid, 256>>>(hw_p, alo_p, ahi_p, b1, feat_p);
    }
    // ------- Layer 2: feat[.,256] @ W2^T -> hw[.,256] -------
    {
        dim3 grid(HC1 / 64, (NNODES + 63) / 64);
        k_gemm_nt<<<grid, gemm_blk>>>(feat_p, W2, hw_p, NNODES, HC1, HC1);
        k_attn_coef<HEADS, HIDDEN><<<warps_grid, 256>>>(hw_p, as2, ad2, alo_p, ahi_p);
        k_aggregate<HEADS, HIDDEN><<<warps_grid, 256>>>(hw_p, alo_p, ahi_p, b2, feat_p);
    }
    // ------- Layer 3: feat[.,256] @ W3^T -> hw[.,64], heads=1 -------
    {
        dim3 grid(HIDDEN / 64, (NNODES + 63) / 64);
        k_gemm_nt<<<grid, gemm_blk>>>(feat_p, W3, hw_p, NNODES, HIDDEN, HC1);
        k_attn_coef<1, HIDDEN><<<warps_grid, 256>>>(hw_p, as3, ad3, alo_p, ahi_p);
        k_aggregate<1, HIDDEN><<<warps_grid, 256>>>(hw_p, alo_p, ahi_p, b3, feat_p);
    }

    // ------- Pool + MLP heads -------
    k_pool<<<warps_grid, 256>>>(feat_p, batch);
    k_mlp<<<(NGRAPHS * 32 + 255) / 256, 256>>>(Wc1, bc1, Wc2, bc2, Wr1, br1, Wr2, br2, out);
}

// round 3
// speedup vs baseline: 1.5175x; 1.5175x over previous
#include <cuda_runtime.h>
#include <cuda_bf16.h>
#include <stdint.h>
#include <math.h>

// ---------------------------------------------------------------------------
// Problem constants
// ---------------------------------------------------------------------------
#define NNODES   50000
#define NEDGES   800000
#define IN_DIM   128
#define HIDDEN   64
#define HEADS    4
#define NGRAPHS  256
#define HC1      256   // HEADS*HIDDEN
#define NEG_SLOPE 0.2f

// ---------------------------------------------------------------------------
// Device scratch
// ---------------------------------------------------------------------------
__device__ float g_hw[(size_t)NNODES * HC1];
__device__ float g_feat[(size_t)NNODES * HC1];
__device__ float g_alo[NNODES * HEADS];
__device__ float g_ahi[NNODES * HEADS];
__device__ int   g_off[NNODES + 1];
__device__ int   g_fill[NNODES];
__device__ int   g_csr[NEDGES];
__device__ float g_pool[NGRAPHS * HIDDEN];
__device__ float g_cnt[NGRAPHS];

// ---------------------------------------------------------------------------
// Small utility kernels
// ---------------------------------------------------------------------------
__global__ void k_zero_csr() {
    int i = blockIdx.x * blockDim.x + threadIdx.x;
    if (i <= NNODES) g_off[i] = 0;
    if (i < NGRAPHS * HIDDEN) g_pool[i] = 0.f;
    if (i < NGRAPHS) g_cnt[i] = 0.f;
}

__global__ void k_hist(const int* __restrict__ dst) {
    int e = blockIdx.x * blockDim.x + threadIdx.x;
    if (e < NEDGES) atomicAdd(&g_off[dst[e] + 1], 1);
}

__global__ void k_scan() {
    __shared__ int s[1024];
    __shared__ int carry;
    int t = threadIdx.x;
    if (t == 0) carry = 0;
    __syncthreads();
    for (int base = 0; base < NNODES; base += 1024) {
        int i = base + t;
        int v = (i < NNODES) ? g_off[i + 1] : 0;
        s[t] = v; __syncthreads();
        #pragma unroll
        for (int off = 1; off < 1024; off <<= 1) {
            int add = (t >= off) ? s[t - off] : 0;
            __syncthreads();
            s[t] += add;
            __syncthreads();
        }
        if (i < NNODES) g_off[i + 1] = carry + s[t];
        __syncthreads();
        if (t == 0) carry += s[1023];
        __syncthreads();
    }
}

__global__ void k_fill_init() {
    int i = blockIdx.x * blockDim.x + threadIdx.x;
    if (i < NNODES) g_fill[i] = g_off[i];
}

__global__ void k_scatter(const int* __restrict__ src, const int* __restrict__ dst) {
    int e = blockIdx.x * blockDim.x + threadIdx.x;
    if (e < NEDGES) {
        int p = atomicAdd(&g_fill[dst[e]], 1);
        g_csr[p] = src[e];
    }
}

// ---------------------------------------------------------------------------
// TF32 tensor-core GEMM: C[M,Nn] = A[M,K] @ B[Nn,K]^T  (NT, both K-contig)
// Block 128x64, BK=16, 8 warps (4m x 2n), warp tile 32x32.
// 3xTF32 split for near-fp32 accuracy.
// ---------------------------------------------------------------------------
__device__ __forceinline__ float tf32_round(float x) {
    unsigned int u;
    asm("cvt.rna.tf32.f32 %0, %1;" : "=r"(u) : "f"(x));
    return __uint_as_float(u);
}

__device__ __forceinline__ void mma_tf32(float* d, const unsigned int* a, const unsigned int* b) {
    asm volatile(
        "mma.sync.aligned.m16n8k8.row.col.f32.tf32.tf32.f32 "
        "{%0,%1,%2,%3}, {%4,%5,%6,%7}, {%8,%9}, {%0,%1,%2,%3};\n"
        : "+f"(d[0]), "+f"(d[1]), "+f"(d[2]), "+f"(d[3])
        : "r"(a[0]), "r"(a[1]), "r"(a[2]), "r"(a[3]), "r"(b[0]), "r"(b[1]));
}

#define GBM 128
#define GBN 64
#define GBK 16
#define GPAD 20   // row stride in floats

__global__ __launch_bounds__(256) void k_gemm_tf32(
    const float* __restrict__ A, const float* __restrict__ B,
    float* __restrict__ C, int M, int Nn, int K) {
    __shared__ float sAh[GBM * GPAD], sAl[GBM * GPAD];
    __shared__ float sBh[GBN * GPAD], sBl[GBN * GPAD];

    int t = threadIdx.x;
    int lane = t & 31, warp = t >> 5;
    int wm = warp >> 1, wn = warp & 1;          // 4 x 2 warp grid
    int m0 = blockIdx.y * GBM, n0 = blockIdx.x * GBN;

    float acc[2][4][4];
    #pragma unroll
    for (int i = 0; i < 2; i++)
        #pragma unroll
        for (int j = 0; j < 4; j++)
            #pragma unroll
            for (int k = 0; k < 4; k++) acc[i][j][k] = 0.f;

    for (int k0 = 0; k0 < K; k0 += GBK) {
        // load A tile 128x16 (512 float4, 2 per thread)
        #pragma unroll
        for (int i = 0; i < 2; i++) {
            int lin = t + i * 256;              // 0..511
            int row = lin >> 2, c4 = (lin & 3) * 4;
            float4 v = make_float4(0.f, 0.f, 0.f, 0.f);
            int gm = m0 + row;
            if (gm < M) v = *(const float4*)&A[(size_t)gm * K + k0 + c4];
            float4 h, l;
            h.x = tf32_round(v.x); l.x = v.x - h.x;
            h.y = tf32_round(v.y); l.y = v.y - h.y;
            h.z = tf32_round(v.z); l.z = v.z - h.z;
            h.w = tf32_round(v.w); l.w = v.w - h.w;
            *(float4*)&sAh[row * GPAD + c4] = h;
            *(float4*)&sAl[row * GPAD + c4] = l;
        }
        // load B tile 64x16 (256 float4, 1 per thread); Nn % 64 == 0 always
        {
            int row = t >> 2, c4 = (t & 3) * 4;
            float4 v = *(const float4*)&B[(size_t)(n0 + row) * K + k0 + c4];
            float4 h, l;
            h.x = tf32_round(v.x); l.x = v.x - h.x;
            h.y = tf32_round(v.y); l.y = v.y - h.y;
            h.z = tf32_round(v.z); l.z = v.z - h.z;
            h.w = tf32_round(v.w); l.w = v.w - h.w;
            *(float4*)&sBh[row * GPAD + c4] = h;
            *(float4*)&sBl[row * GPAD + c4] = l;
        }
        __syncthreads();

        #pragma unroll
        for (int ks = 0; ks < 2; ks++) {
            int kb = ks * 8;
            unsigned int ah[2][4], al[2][4];
            #pragma unroll
            for (int mi = 0; mi < 2; mi++) {
                int r = wm * 32 + mi * 16 + (lane >> 2);
                int c = kb + (lane & 3);
                ah[mi][0] = __float_as_uint(sAh[r * GPAD + c]);
                ah[mi][1] = __float_as_uint(sAh[(r + 8) * GPAD + c]);
                ah[mi][2] = __float_as_uint(sAh[r * GPAD + c + 4]);
                ah[mi][3] = __float_as_uint(sAh[(r + 8) * GPAD + c + 4]);
                al[mi][0] = __float_as_uint(sAl[r * GPAD + c]);
                al[mi][1] = __float_as_uint(sAl[(r + 8) * GPAD + c]);
                al[mi][2] = __float_as_uint(sAl[r * GPAD + c + 4]);
                al[mi][3] = __float_as_uint(sAl[(r + 8) * GPAD + c + 4]);
            }
            unsigned int bh[4][2], bl[4][2];
            #pragma unroll
            for (int ni = 0; ni < 4; ni++) {
                int n = wn * 32 + ni * 8 + (lane >> 2);
                int c = kb + (lane & 3);
                bh[ni][0] = __float_as_uint(sBh[n * GPAD + c]);
                bh[ni][1] = __float_as_uint(sBh[n * GPAD + c + 4]);
                bl[ni][0] = __float_as_uint(sBl[n * GPAD + c]);
                bl[ni][1] = __float_as_uint(sBl[n * GPAD + c + 4]);
            }
            #pragma unroll
            for (int mi = 0; mi < 2; mi++)
                #pragma unroll
                for (int ni = 0; ni < 4; ni++) {
                    mma_tf32(acc[mi][ni], ah[mi], bh[ni]);   // hi*hi
                    mma_tf32(acc[mi][ni], ah[mi], bl[ni]);   // hi*lo
                    mma_tf32(acc[mi][ni], al[mi], bh[ni]);   // lo*hi
                }
        }
        __syncthreads();
    }

    // epilogue
    #pragma unroll
    for (int mi = 0; mi < 2; mi++) {
        int r0 = m0 + wm * 32 + mi * 16 + (lane >> 2);
        #pragma unroll
        for (int ni = 0; ni < 4; ni++) {
            int c = n0 + wn * 32 + ni * 8 + (lane & 3) * 2;
            if (r0 < M)
                *(float2*)&C[(size_t)r0 * Nn + c] = make_float2(acc[mi][ni][0], acc[mi][ni][1]);
            if (r0 + 8 < M)
                *(float2*)&C[(size_t)(r0 + 8) * Nn + c] = make_float2(acc[mi][ni][2], acc[mi][ni][3]);
        }
    }
}

// ---------------------------------------------------------------------------
// Attention coefficients: one warp per node.
// ---------------------------------------------------------------------------
template <int H, int C>
__global__ void k_attn_coef(const float* __restrict__ h,
                            const float* __restrict__ a_src,
                            const float* __restrict__ a_dst,
                            float* __restrict__ alo, float* __restrict__ ahi) {
    const int HCn = H * C;
    const int FPL = HCn / 32;
    const int LPH = 32 / H;
    int warp = (blockIdx.x * blockDim.x + threadIdx.x) >> 5;
    int lane = threadIdx.x & 31;
    if (warp >= NNODES) return;
    const float* hr = h + (size_t)warp * HCn + lane * FPL;
    float s_lo = 0.f, s_hi = 0.f;
    #pragma unroll
    for (int i = 0; i < FPL; i++) {
        float v = hr[i];
        s_lo += v * a_src[lane * FPL + i];
        s_hi += v * a_dst[lane * FPL + i];
    }
    #pragma unroll
    for (int off = LPH / 2; off > 0; off >>= 1) {
        s_lo += __shfl_down_sync(0xffffffffu, s_lo, off);
        s_hi += __shfl_down_sync(0xffffffffu, s_hi, off);
    }
    if ((lane % LPH) == 0) {
        int hh = lane / LPH;
        alo[warp * H + hh] = s_lo;
        ahi[warp * H + hh] = s_hi;
    }
}

// ---------------------------------------------------------------------------
// Aggregation with segment softmax. One warp per dst node.
// ---------------------------------------------------------------------------
__device__ __forceinline__ float lrelu(float x) { return x > 0.f ? x : NEG_SLOPE * x; }

template <int H, int C>
__global__ void k_aggregate(const float* __restrict__ hw,
                            const float* __restrict__ alo,
                            const float* __restrict__ ahi,
                            const float* __restrict__ bias,
                            float* __restrict__ out) {
    const int HCn = H * C;
    const int FPL = HCn / 32;
    const int LPH = 32 / H;
    int warp = (blockIdx.x * blockDim.x + threadIdx.x) >> 5;
    int lane = threadIdx.x & 31;
    if (warp >= NNODES) return;
    int n   = warp;
    int beg = g_off[n], deg = g_off[n + 1] - beg;

    float ahin[H];
    #pragma unroll
    for (int hh = 0; hh < H; hh++) ahin[hh] = ahi[n * H + hh];

    float mx[H];
    #pragma unroll
    for (int hh = 0; hh < H; hh++) mx[hh] = -1e30f;
    for (int j = lane; j <= deg; j += 32) {
        int src = (j < deg) ? g_csr[beg + j] : n;
        #pragma unroll
        for (int hh = 0; hh < H; hh++) {
            float e = lrelu(alo[src * H + hh] + ahin[hh]);
            mx[hh] = fmaxf(mx[hh], e);
        }
    }
    #pragma unroll
    for (int off = 16; off > 0; off >>= 1)
        #pragma unroll
        for (int hh = 0; hh < H; hh++)
            mx[hh] = fmaxf(mx[hh], __shfl_xor_sync(0xffffffffu, mx[hh], off));

    float den[H];
    #pragma unroll
    for (int hh = 0; hh < H; hh++) den[hh] = 0.f;
    for (int j = lane; j <= deg; j += 32) {
        int src = (j < deg) ? g_csr[beg + j] : n;
        #pragma unroll
        for (int hh = 0; hh < H; hh++) {
            float e = lrelu(alo[src * H + hh] + ahin[hh]);
            den[hh] += __expf(e - mx[hh]);
        }
    }
    #pragma unroll
    for (int off = 16; off > 0; off >>= 1)
        #pragma unroll
        for (int hh = 0; hh < H; hh++)
            den[hh] += __shfl_xor_sync(0xffffffffu, den[hh], off);

    int hh_l = lane / LPH;
    float my_m = 0.f, my_d = 0.f, my_a = 0.f;
    #pragma unroll
    for (int hh = 0; hh < H; hh++)
        if (hh == hh_l) { my_m = mx[hh]; my_d = den[hh]; my_a = ahin[hh]; }
    float inv_d = 1.f / (my_d + 1e-16f);

    float acc[FPL];
    #pragma unroll
    for (int i = 0; i < FPL; i++) acc[i] = 0.f;
    for (int j = 0; j <= deg; j++) {
        int src = (j < deg) ? g_csr[beg + j] : n;
        float e = lrelu(alo[src * H + hh_l] + my_a);
        float w = __expf(e - my_m) * inv_d;
        const float* hp = hw + (size_t)src * HCn + lane * FPL;
        if (FPL == 8) {
            float4 v0 = *(const float4*)(hp);
            float4 v1 = *(const float4*)(hp + 4);
            acc[0] += w * v0.x; acc[1] += w * v0.y; acc[2] += w * v0.z; acc[3] += w * v0.w;
            acc[4] += w * v1.x; acc[5] += w * v1.y; acc[6] += w * v1.z; acc[7] += w * v1.w;
        } else {
            float2 v0 = *(const float2*)(hp);
            acc[0] += w * v0.x;
            if (FPL > 1) acc[1] += w * v0.y;
        }
    }
    #pragma unroll
    for (int i = 0; i < FPL; i++) {
        float v = acc[i] + bias[lane * FPL + i];
        v = (v > 0.f) ? v : (expm1f(v));
        out[(size_t)n * HCn + lane * FPL + i] = v;
    }
}

// ---------------------------------------------------------------------------
// Global mean pool
// ---------------------------------------------------------------------------
__global__ void k_pool(const float* __restrict__ h3, const int* __restrict__ batch) {
    int warp = (blockIdx.x * blockDim.x + threadIdx.x) >> 5;
    int lane = threadIdx.x & 31;
    if (warp >= NNODES) return;
    int b = batch[warp];
    atomicAdd(&g_pool[b * HIDDEN + lane],      h3[(size_t)warp * HIDDEN + lane]);
    atomicAdd(&g_pool[b * HIDDEN + lane + 32], h3[(size_t)warp * HIDDEN + lane + 32]);
    if (lane == 0) atomicAdd(&g_cnt[b], 1.f);
}

// ---------------------------------------------------------------------------
// Heads MLP: one warp per graph
// ---------------------------------------------------------------------------
__global__ void k_mlp(const float* __restrict__ Wc1, const float* __restrict__ bc1,
                      const float* __restrict__ Wc2, const float* __restrict__ bc2,
                      const float* __restrict__ Wr1, const float* __restrict__ br1,
                      const float* __restrict__ Wr2, const float* __restrict__ br2,
                      float* __restrict__ out) {
    int warp = (blockIdx.x * blockDim.x + threadIdx.x) >> 5;
    int lane = threadIdx.x & 31;
    if (warp >= NGRAPHS) return;
    float inv_cnt = 1.f / fmaxf(g_cnt[warp], 1.f);
    const float* gp = &g_pool[warp * HIDDEN];

    {
        float h0 = bc1[lane], h1 = bc1[lane + 32];
        for (int c = 0; c < HIDDEN; c++) {
            float gc = gp[c] * inv_cnt;
            h0 += Wc1[lane * HIDDEN + c] * gc;
            h1 += Wc1[(lane + 32) * HIDDEN + c] * gc;
        }
        h0 = fmaxf(h0, 0.f); h1 = fmaxf(h1, 0.f);
        float s = Wc2[lane] * h0 + Wc2[lane + 32] * h1;
        #pragma unroll
        for (int off = 16; off > 0; off >>= 1) s += __shfl_xor_sync(0xffffffffu, s, off);
        if (lane == 0) out[warp] = s + bc2[0];
    }
    {
        float h0 = br1[lane], h1 = br1[lane + 32];
        for (int c = 0; c < HIDDEN; c++) {
            float gc = gp[c] * inv_cnt;
            h0 += Wr1[lane * HIDDEN + c] * gc;
            h1 += Wr1[(lane + 32) * HIDDEN + c] * gc;
        }
        h0 = fmaxf(h0, 0.f); h1 = fmaxf(h1, 0.f);
        float s = Wr2[lane] * h0 + Wr2[lane + 32] * h1;
        #pragma unroll
        for (int off = 16; off > 0; off >>= 1) s += __shfl_xor_sync(0xffffffffu, s, off);
        if (lane == 0) out[NGRAPHS + warp] = s + br2[0];
    }
}

// ---------------------------------------------------------------------------
// Launch
// ---------------------------------------------------------------------------
extern "C" void kernel_launch(void* const* d_in, const int* in_sizes, int n_in,
                              void* d_out, int out_size) {
    const float* x     = (const float*)d_in[0];
    const int*   ei    = (const int*)d_in[1];
    const int*   batch = (const int*)d_in[2];
    const float* W1  = (const float*)d_in[3];
    const float* as1 = (const float*)d_in[4];
    const float* ad1 = (const float*)d_in[5];
    const float* b1  = (const float*)d_in[6];
    const float* W2  = (const float*)d_in[7];
    const float* as2 = (const float*)d_in[8];
    const float* ad2 = (const float*)d_in[9];
    const float* b2  = (const float*)d_in[10];
    const float* W3  = (const float*)d_in[11];
    const float* as3 = (const float*)d_in[12];
    const float* ad3 = (const float*)d_in[13];
    const float* b3  = (const float*)d_in[14];
    const float* Wc1 = (const float*)d_in[15];
    const float* bc1 = (const float*)d_in[16];
    const float* Wc2 = (const float*)d_in[17];
    const float* bc2 = (const float*)d_in[18];
    const float* Wr1 = (const float*)d_in[19];
    const float* br1 = (const float*)d_in[20];
    const float* Wr2 = (const float*)d_in[21];
    const float* br2 = (const float*)d_in[22];
    float* out = (float*)d_out;

    const int* srcp = ei;
    const int* dstp = ei + NEDGES;

    k_zero_csr<<<(NNODES + 256) / 256, 256>>>();
    k_hist<<<(NEDGES + 255) / 256, 256>>>(dstp);
    k_scan<<<1, 1024>>>();
    k_fill_init<<<(NNODES + 255) / 256, 256>>>();
    k_scatter<<<(NEDGES + 255) / 256, 256>>>(srcp, dstp);

    float* hw_p   = nullptr; cudaGetSymbolAddress((void**)&hw_p,   g_hw);
    float* feat_p = nullptr; cudaGetSymbolAddress((void**)&feat_p, g_feat);
    float* alo_p  = nullptr; cudaGetSymbolAddress((void**)&alo_p,  g_alo);
    float* ahi_p  = nullptr; cudaGetSymbolAddress((void**)&ahi_p,  g_ahi);

    const int warps_grid = (NNODES * 32 + 255) / 256;
    const int mblocks = (NNODES + GBM - 1) / GBM;

    // Layer 1
    {
        dim3 grid(HC1 / GBN, mblocks);
        k_gemm_tf32<<<grid, 256>>>(x, W1, hw_p, NNODES, HC1, IN_DIM);
        k_attn_coef<HEADS, HIDDEN><<<warps_grid, 256>>>(hw_p, as1, ad1, alo_p, ahi_p);
        k_aggregate<HEADS, HIDDEN><<<warps_grid, 256>>>(hw_p, alo_p, ahi_p, b1, feat_p);
    }
    // Layer 2
    {
        dim3 grid(HC1 / GBN, mblocks);
        k_gemm_tf32<<<grid, 256>>>(feat_p, W2, hw_p, NNODES, HC1, HC1);
        k_attn_coef<HEADS, HIDDEN><<<warps_grid, 256>>>(hw_p, as2, ad2, alo_p, ahi_p);
        k_aggregate<HEADS, HIDDEN><<<warps_grid, 256>>>(hw_p, alo_p, ahi_p, b2, feat_p);
    }
    // Layer 3 (heads=1, out dim 64)
    {
        dim3 grid(HIDDEN / GBN, mblocks);
        k_gemm_tf32<<<grid, 256>>>(feat_p, W3, hw_p, NNODES, HIDDEN, HC1);
        k_attn_coef<1, HIDDEN><<<warps_grid, 256>>>(hw_p, as3, ad3, alo_p, ahi_p);
        k_aggregate<1, HIDDEN><<<warps_grid, 256>>>(hw_p, alo_p, ahi_p, b3, feat_p);
    }

    k_pool<<<warps_grid, 256>>>(feat_p, batch);
    k_mlp<<<(NGRAPHS * 32 + 255) / 256, 256>>>(Wc1, bc1, Wc2, bc2, Wr1, br1, Wr2, br2, out);
}

// round 4
// speedup vs baseline: 1.9184x; 1.2642x over previous
#include <cuda_runtime.h>
#include <cuda_bf16.h>
#include <stdint.h>
#include <math.h>

// ---------------------------------------------------------------------------
// Problem constants
// ---------------------------------------------------------------------------
#define NNODES   50000
#define NEDGES   800000
#define IN_DIM   128
#define HIDDEN   64
#define HEADS    4
#define NGRAPHS  256
#define HC1      256
#define NEG_SLOPE 0.2f

// ---------------------------------------------------------------------------
// Device scratch
// ---------------------------------------------------------------------------
__device__ float g_hw[(size_t)NNODES * HC1];
__device__ float g_feat[(size_t)NNODES * HC1];
__device__ float g_alo[NNODES * HEADS];
__device__ float g_ahi[NNODES * HEADS];
__device__ int   g_off[NNODES + 1];
__device__ int   g_fill[NNODES];
__device__ int   g_csr[NEDGES];
__device__ float g_pool[NGRAPHS * HIDDEN];
__device__ float g_cnt[NGRAPHS];

// ---------------------------------------------------------------------------
// Small utility kernels
// ---------------------------------------------------------------------------
__global__ void k_zero_csr() {
    int i = blockIdx.x * blockDim.x + threadIdx.x;
    if (i <= NNODES) g_off[i] = 0;
    if (i < NGRAPHS * HIDDEN) g_pool[i] = 0.f;
    if (i < NGRAPHS) g_cnt[i] = 0.f;
}

__global__ void k_hist(const int* __restrict__ dst) {
    int e = blockIdx.x * blockDim.x + threadIdx.x;
    if (e < NEDGES) atomicAdd(&g_off[dst[e] + 1], 1);
}

__global__ void k_scan() {
    __shared__ int s[1024];
    __shared__ int carry;
    int t = threadIdx.x;
    if (t == 0) carry = 0;
    __syncthreads();
    for (int base = 0; base < NNODES; base += 1024) {
        int i = base + t;
        int v = (i < NNODES) ? g_off[i + 1] : 0;
        s[t] = v; __syncthreads();
        #pragma unroll
        for (int off = 1; off < 1024; off <<= 1) {
            int add = (t >= off) ? s[t - off] : 0;
            __syncthreads();
            s[t] += add;
            __syncthreads();
        }
        if (i < NNODES) g_off[i + 1] = carry + s[t];
        __syncthreads();
        if (t == 0) carry += s[1023];
        __syncthreads();
    }
}

__global__ void k_fill_init() {
    int i = blockIdx.x * blockDim.x + threadIdx.x;
    if (i < NNODES) g_fill[i] = g_off[i];
}

__global__ void k_scatter(const int* __restrict__ src, const int* __restrict__ dst) {
    int e = blockIdx.x * blockDim.x + threadIdx.x;
    if (e < NEDGES) {
        int p = atomicAdd(&g_fill[dst[e]], 1);
        g_csr[p] = src[e];
    }
}

// ---------------------------------------------------------------------------
// bf16 3-split tensor-core GEMM + fused attention-coefficient epilogue.
// C[M,Nn] = A[M,K] @ B[Nn,K]^T ; also alo/ahi[row,head] = C_tile . a_src/a_dst
// Block 128x64 (n-block == one head), BK=16, 8 warps (4m x 2n), warp 32x32.
// ---------------------------------------------------------------------------
__device__ __forceinline__ void mma_bf16(float* d, const unsigned int* a, const unsigned int* b) {
    asm volatile(
        "mma.sync.aligned.m16n8k16.row.col.f32.bf16.bf16.f32 "
        "{%0,%1,%2,%3}, {%4,%5,%6,%7}, {%8,%9}, {%0,%1,%2,%3};\n"
        : "+f"(d[0]), "+f"(d[1]), "+f"(d[2]), "+f"(d[3])
        : "r"(a[0]), "r"(a[1]), "r"(a[2]), "r"(a[3]), "r"(b[0]), "r"(b[1]));
}

__device__ __forceinline__ unsigned int pack_bf2(__nv_bfloat16 a, __nv_bfloat16 b) {
    __nv_bfloat162 t(a, b);
    return *(unsigned int*)&t;
}

#define GBM 128
#define GBN 64
#define GBK 16
#define WSTR 12   // word stride per row (words of 2 bf16); 12q+t is a perfect bank permutation

__global__ __launch_bounds__(256) void k_gemm_bf16(
    const float* __restrict__ A, const float* __restrict__ B,
    float* __restrict__ C, int M, int Nn, int K,
    const float* __restrict__ a_src, const float* __restrict__ a_dst,
    float* __restrict__ alo, float* __restrict__ ahi, int H) {
    __shared__ unsigned int sAh[GBM * WSTR], sAl[GBM * WSTR];
    __shared__ unsigned int sBh[GBN * WSTR], sBl[GBN * WSTR];
    __shared__ float s_alo[GBM], s_ahi[GBM];

    int t = threadIdx.x;
    int lane = t & 31, warp = t >> 5;
    int wm = warp >> 1, wn = warp & 1;
    int m0 = blockIdx.y * GBM, n0 = blockIdx.x * GBN;
    int head = blockIdx.x;            // Nn/64 blocks in x == head index

    if (t < GBM) { s_alo[t] = 0.f; s_ahi[t] = 0.f; }

    float acc[2][4][4];
    #pragma unroll
    for (int i = 0; i < 2; i++)
        #pragma unroll
        for (int j = 0; j < 4; j++)
            #pragma unroll
            for (int k = 0; k < 4; k++) acc[i][j][k] = 0.f;

    for (int k0 = 0; k0 < K; k0 += GBK) {
        // A tile 128x16 floats -> split bf16 (512 float4 loads, 2/thread)
        #pragma unroll
        for (int i = 0; i < 2; i++) {
            int lin = t + i * 256;
            int row = lin >> 2, c4 = (lin & 3) * 4;    // float col 0,4,8,12
            float4 v = make_float4(0.f, 0.f, 0.f, 0.f);
            int gm = m0 + row;
            if (gm < M) v = *(const float4*)&A[(size_t)gm * K + k0 + c4];
            __nv_bfloat16 hx = __float2bfloat16(v.x), hy = __float2bfloat16(v.y);
            __nv_bfloat16 hz = __float2bfloat16(v.z), hw4 = __float2bfloat16(v.w);
            __nv_bfloat16 lx = __float2bfloat16(v.x - __bfloat162float(hx));
            __nv_bfloat16 ly = __float2bfloat16(v.y - __bfloat162float(hy));
            __nv_bfloat16 lz = __float2bfloat16(v.z - __bfloat162float(hz));
            __nv_bfloat16 lw = __float2bfloat16(v.w - __bfloat162float(hw4));
            int w0 = row * WSTR + (c4 >> 1);
            sAh[w0] = pack_bf2(hx, hy); sAh[w0 + 1] = pack_bf2(hz, hw4);
            sAl[w0] = pack_bf2(lx, ly); sAl[w0 + 1] = pack_bf2(lz, lw);
        }
        // B tile 64x16 floats (256 float4 loads, 1/thread); Nn % 64 == 0
        {
            int row = t >> 2, c4 = (t & 3) * 4;
            float4 v = *(const float4*)&B[(size_t)(n0 + row) * K + k0 + c4];
            __nv_bfloat16 hx = __float2bfloat16(v.x), hy = __float2bfloat16(v.y);
            __nv_bfloat16 hz = __float2bfloat16(v.z), hw4 = __float2bfloat16(v.w);
            __nv_bfloat16 lx = __float2bfloat16(v.x - __bfloat162float(hx));
            __nv_bfloat16 ly = __float2bfloat16(v.y - __bfloat162float(hy));
            __nv_bfloat16 lz = __float2bfloat16(v.z - __bfloat162float(hz));
            __nv_bfloat16 lw = __float2bfloat16(v.w - __bfloat162float(hw4));
            int w0 = row * WSTR + (c4 >> 1);
            sBh[w0] = pack_bf2(hx, hy); sBh[w0 + 1] = pack_bf2(hz, hw4);
            sBl[w0] = pack_bf2(lx, ly); sBl[w0 + 1] = pack_bf2(lz, lw);
        }
        __syncthreads();

        unsigned int ah[2][4], al[2][4];
        #pragma unroll
        for (int mi = 0; mi < 2; mi++) {
            int r = wm * 32 + mi * 16 + (lane >> 2);
            int c = lane & 3;
            ah[mi][0] = sAh[r * WSTR + c];
            ah[mi][1] = sAh[(r + 8) * WSTR + c];
            ah[mi][2] = sAh[r * WSTR + c + 4];
            ah[mi][3] = sAh[(r + 8) * WSTR + c + 4];
            al[mi][0] = sAl[r * WSTR + c];
            al[mi][1] = sAl[(r + 8) * WSTR + c];
            al[mi][2] = sAl[r * WSTR + c + 4];
            al[mi][3] = sAl[(r + 8) * WSTR + c + 4];
        }
        unsigned int bh[4][2], bl[4][2];
        #pragma unroll
        for (int ni = 0; ni < 4; ni++) {
            int n = wn * 32 + ni * 8 + (lane >> 2);
            int c = lane & 3;
            bh[ni][0] = sBh[n * WSTR + c];
            bh[ni][1] = sBh[n * WSTR + c + 4];
            bl[ni][0] = sBl[n * WSTR + c];
            bl[ni][1] = sBl[n * WSTR + c + 4];
        }
        #pragma unroll
        for (int mi = 0; mi < 2; mi++)
            #pragma unroll
            for (int ni = 0; ni < 4; ni++) {
                mma_bf16(acc[mi][ni], ah[mi], bh[ni]);  // hi*hi
                mma_bf16(acc[mi][ni], ah[mi], bl[ni]);  // hi*lo
                mma_bf16(acc[mi][ni], al[mi], bh[ni]);  // lo*hi
            }
        __syncthreads();
    }

    // ---- epilogue: store C + fused alo/ahi dot products ----
    const float* as_h = a_src + head * 64;
    const float* ad_h = a_dst + head * 64;
    float sl[4] = {0.f, 0.f, 0.f, 0.f};   // (mi, row-half) alo partial
    float sh_[4] = {0.f, 0.f, 0.f, 0.f};  // ahi partial

    #pragma unroll
    for (int mi = 0; mi < 2; mi++) {
        int r0 = m0 + wm * 32 + mi * 16 + (lane >> 2);
        #pragma unroll
        for (int ni = 0; ni < 4; ni++) {
            int cl = wn * 32 + ni * 8 + (lane & 3) * 2;  // local col in [0,64)
            float as0 = as_h[cl], as1 = as_h[cl + 1];
            float ad0 = ad_h[cl], ad1 = ad_h[cl + 1];
            sl[mi * 2 + 0] += acc[mi][ni][0] * as0 + acc[mi][ni][1] * as1;
            sh_[mi * 2 + 0] += acc[mi][ni][0] * ad0 + acc[mi][ni][1] * ad1;
            sl[mi * 2 + 1] += acc[mi][ni][2] * as0 + acc[mi][ni][3] * as1;
            sh_[mi * 2 + 1] += acc[mi][ni][2] * ad0 + acc[mi][ni][3] * ad1;
            int c = n0 + cl;
            if (r0 < M)
                *(float2*)&C[(size_t)r0 * Nn + c] = make_float2(acc[mi][ni][0], acc[mi][ni][1]);
            if (r0 + 8 < M)
                *(float2*)&C[(size_t)(r0 + 8) * Nn + c] = make_float2(acc[mi][ni][2], acc[mi][ni][3]);
        }
    }
    // reduce over the 4 lanes of the quad
    #pragma unroll
    for (int off = 1; off <= 2; off <<= 1)
        #pragma unroll
        for (int i = 0; i < 4; i++) {
            sl[i] += __shfl_xor_sync(0xffffffffu, sl[i], off);
            sh_[i] += __shfl_xor_sync(0xffffffffu, sh_[i], off);
        }
    if ((lane & 3) == 0) {
        #pragma unroll
        for (int mi = 0; mi < 2; mi++) {
            int rl = wm * 32 + mi * 16 + (lane >> 2);
            atomicAdd(&s_alo[rl], sl[mi * 2]);
            atomicAdd(&s_ahi[rl], sh_[mi * 2]);
            atomicAdd(&s_alo[rl + 8], sl[mi * 2 + 1]);
            atomicAdd(&s_ahi[rl + 8], sh_[mi * 2 + 1]);
        }
    }
    __syncthreads();
    if (t < GBM && m0 + t < M) {
        alo[(m0 + t) * H + head] = s_alo[t];
        ahi[(m0 + t) * H + head] = s_ahi[t];
    }
}

// ---------------------------------------------------------------------------
// Aggregation with online segment softmax. One warp per dst node.
// ---------------------------------------------------------------------------
__device__ __forceinline__ float lrelu(float x) { return x > 0.f ? x : NEG_SLOPE * x; }

template <int H, int C>
__global__ void k_aggregate(const float* __restrict__ hw,
                            const float* __restrict__ alo,
                            const float* __restrict__ ahi,
                            const float* __restrict__ bias,
                            float* __restrict__ out) {
    const int HCn = H * C;
    const int FPL = HCn / 32;
    const int LPH = 32 / H;
    int warp = (blockIdx.x * blockDim.x + threadIdx.x) >> 5;
    int lane = threadIdx.x & 31;
    if (warp >= NNODES) return;
    int n   = warp;
    int beg = g_off[n], deg = g_off[n + 1] - beg;

    float ahin[H];
    #pragma unroll
    for (int hh = 0; hh < H; hh++) ahin[hh] = ahi[n * H + hh];

    // online softmax: running (m, d) per head
    float mx[H], den[H];
    #pragma unroll
    for (int hh = 0; hh < H; hh++) { mx[hh] = -1e30f; den[hh] = 0.f; }
    for (int j = lane; j <= deg; j += 32) {
        int src = (j < deg) ? g_csr[beg + j] : n;
        #pragma unroll
        for (int hh = 0; hh < H; hh++) {
            float e = lrelu(alo[src * H + hh] + ahin[hh]);
            float mn = fmaxf(mx[hh], e);
            den[hh] = den[hh] * __expf(mx[hh] - mn) + __expf(e - mn);
            mx[hh] = mn;
        }
    }
    #pragma unroll
    for (int off = 16; off > 0; off >>= 1)
        #pragma unroll
        for (int hh = 0; hh < H; hh++) {
            float mo = __shfl_xor_sync(0xffffffffu, mx[hh], off);
            float doo = __shfl_xor_sync(0xffffffffu, den[hh], off);
            float mn = fmaxf(mx[hh], mo);
            den[hh] = den[hh] * __expf(mx[hh] - mn) + doo * __expf(mo - mn);
            mx[hh] = mn;
        }

    int hh_l = lane / LPH;
    float my_m = 0.f, my_d = 0.f, my_a = 0.f;
    #pragma unroll
    for (int hh = 0; hh < H; hh++)
        if (hh == hh_l) { my_m = mx[hh]; my_d = den[hh]; my_a = ahin[hh]; }
    float inv_d = 1.f / (my_d + 1e-16f);

    float acc[FPL];
    #pragma unroll
    for (int i = 0; i < FPL; i++) acc[i] = 0.f;
    for (int j = 0; j <= deg; j++) {
        int src = (j < deg) ? g_csr[beg + j] : n;
        float e = lrelu(alo[src * H + hh_l] + my_a);
        float w = __expf(e - my_m) * inv_d;
        const float* hp = hw + (size_t)src * HCn + lane * FPL;
        if (FPL == 8) {
            float4 v0 = *(const float4*)(hp);
            float4 v1 = *(const float4*)(hp + 4);
            acc[0] += w * v0.x; acc[1] += w * v0.y; acc[2] += w * v0.z; acc[3] += w * v0.w;
            acc[4] += w * v1.x; acc[5] += w * v1.y; acc[6] += w * v1.z; acc[7] += w * v1.w;
        } else {
            float2 v0 = *(const float2*)(hp);
            acc[0] += w * v0.x;
            if (FPL > 1) acc[1] += w * v0.y;
        }
    }
    #pragma unroll
    for (int i = 0; i < FPL; i++) {
        float v = acc[i] + bias[lane * FPL + i];
        v = (v > 0.f) ? v : (expm1f(v));
        out[(size_t)n * HCn + lane * FPL + i] = v;
    }
}

// ---------------------------------------------------------------------------
// Global mean pool
// ---------------------------------------------------------------------------
__global__ void k_pool(const float* __restrict__ h3, const int* __restrict__ batch) {
    int warp = (blockIdx.x * blockDim.x + threadIdx.x) >> 5;
    int lane = threadIdx.x & 31;
    if (warp >= NNODES) return;
    int b = batch[warp];
    atomicAdd(&g_pool[b * HIDDEN + lane],      h3[(size_t)warp * HIDDEN + lane]);
    atomicAdd(&g_pool[b * HIDDEN + lane + 32], h3[(size_t)warp * HIDDEN + lane + 32]);
    if (lane == 0) atomicAdd(&g_cnt[b], 1.f);
}

// ---------------------------------------------------------------------------
// Heads MLP: one warp per graph
// ---------------------------------------------------------------------------
__global__ void k_mlp(const float* __restrict__ Wc1, const float* __restrict__ bc1,
                      const float* __restrict__ Wc2, const float* __restrict__ bc2,
                      const float* __restrict__ Wr1, const float* __restrict__ br1,
                      const float* __restrict__ Wr2, const float* __restrict__ br2,
                      float* __restrict__ out) {
    int warp = (blockIdx.x * blockDim.x + threadIdx.x) >> 5;
    int lane = threadIdx.x & 31;
    if (warp >= NGRAPHS) return;
    float inv_cnt = 1.f / fmaxf(g_cnt[warp], 1.f);
    const float* gp = &g_pool[warp * HIDDEN];

    {
        float h0 = bc1[lane], h1 = bc1[lane + 32];
        for (int c = 0; c < HIDDEN; c++) {
            float gc = gp[c] * inv_cnt;
            h0 += Wc1[lane * HIDDEN + c] * gc;
            h1 += Wc1[(lane + 32) * HIDDEN + c] * gc;
        }
        h0 = fmaxf(h0, 0.f); h1 = fmaxf(h1, 0.f);
        float s = Wc2[lane] * h0 + Wc2[lane + 32] * h1;
        #pragma unroll
        for (int off = 16; off > 0; off >>= 1) s += __shfl_xor_sync(0xffffffffu, s, off);
        if (lane == 0) out[warp] = s + bc2[0];
    }
    {
        float h0 = br1[lane], h1 = br1[lane + 32];
        for (int c = 0; c < HIDDEN; c++) {
            float gc = gp[c] * inv_cnt;
            h0 += Wr1[lane * HIDDEN + c] * gc;
            h1 += Wr1[(lane + 32) * HIDDEN + c] * gc;
        }
        h0 = fmaxf(h0, 0.f); h1 = fmaxf(h1, 0.f);
        float s = Wr2[lane] * h0 + Wr2[lane + 32] * h1;
        #pragma unroll
        for (int off = 16; off > 0; off >>= 1) s += __shfl_xor_sync(0xffffffffu, s, off);
        if (lane == 0) out[NGRAPHS + warp] = s + br2[0];
    }
}

// ---------------------------------------------------------------------------
// Launch
// ---------------------------------------------------------------------------
extern "C" void kernel_launch(void* const* d_in, const int* in_sizes, int n_in,
                              void* d_out, int out_size) {
    const float* x     = (const float*)d_in[0];
    const int*   ei    = (const int*)d_in[1];
    const int*   batch = (const int*)d_in[2];
    const float* W1  = (const float*)d_in[3];
    const float* as1 = (const float*)d_in[4];
    const float* ad1 = (const float*)d_in[5];
    const float* b1  = (const float*)d_in[6];
    const float* W2  = (const float*)d_in[7];
    const float* as2 = (const float*)d_in[8];
    const float* ad2 = (const float*)d_in[9];
    const float* b2  = (const float*)d_in[10];
    const float* W3  = (const float*)d_in[11];
    const float* as3 = (const float*)d_in[12];
    const float* ad3 = (const float*)d_in[13];
    const float* b3  = (const float*)d_in[14];
    const float* Wc1 = (const float*)d_in[15];
    const float* bc1 = (const float*)d_in[16];
    const float* Wc2 = (const float*)d_in[17];
    const float* bc2 = (const float*)d_in[18];
    const float* Wr1 = (const float*)d_in[19];
    const float* br1 = (const float*)d_in[20];
    const float* Wr2 = (const float*)d_in[21];
    const float* br2 = (const float*)d_in[22];
    float* out = (float*)d_out;

    const int* srcp = ei;
    const int* dstp = ei + NEDGES;

    k_zero_csr<<<(NNODES + 256) / 256, 256>>>();
    k_hist<<<(NEDGES + 255) / 256, 256>>>(dstp);
    k_scan<<<1, 1024>>>();
    k_fill_init<<<(NNODES + 255) / 256, 256>>>();
    k_scatter<<<(NEDGES + 255) / 256, 256>>>(srcp, dstp);

    float* hw_p   = nullptr; cudaGetSymbolAddress((void**)&hw_p,   g_hw);
    float* feat_p = nullptr; cudaGetSymbolAddress((void**)&feat_p, g_feat);
    float* alo_p  = nullptr; cudaGetSymbolAddress((void**)&alo_p,  g_alo);
    float* ahi_p  = nullptr; cudaGetSymbolAddress((void**)&ahi_p,  g_ahi);

    const int warps_grid = (NNODES * 32 + 255) / 256;
    const int mblocks = (NNODES + GBM - 1) / GBM;

    // Layer 1
    {
        dim3 grid(HC1 / GBN, mblocks);
        k_gemm_bf16<<<grid, 256>>>(x, W1, hw_p, NNODES, HC1, IN_DIM, as1, ad1, alo_p, ahi_p, HEADS);
        k_aggregate<HEADS, HIDDEN><<<warps_grid, 256>>>(hw_p, alo_p, ahi_p, b1, feat_p);
    }
    // Layer 2
    {
        dim3 grid(HC1 / GBN, mblocks);
        k_gemm_bf16<<<grid, 256>>>(feat_p, W2, hw_p, NNODES, HC1, HC1, as2, ad2, alo_p, ahi_p, HEADS);
        k_aggregate<HEADS, HIDDEN><<<warps_grid, 256>>>(hw_p, alo_p, ahi_p, b2, feat_p);
    }
    // Layer 3 (heads=1, out dim 64)
    {
        dim3 grid(HIDDEN / GBN, mblocks);
        k_gemm_bf16<<<grid, 256>>>(feat_p, W3, hw_p, NNODES, HIDDEN, HC1, as3, ad3, alo_p, ahi_p, 1);
        k_aggregate<1, HIDDEN><<<warps_grid, 256>>>(hw_p, alo_p, ahi_p, b3, feat_p);
    }

    k_pool<<<warps_grid, 256>>>(feat_p, batch);
    k_mlp<<<(NGRAPHS * 32 + 255) / 256, 256>>>(Wc1, bc1, Wc2, bc2, Wr1, br1, Wr2, br2, out);
}

// round 5
// speedup vs baseline: 2.2569x; 1.1764x over previous
#include <cuda_runtime.h>
#include <cuda_bf16.h>
#include <stdint.h>
#include <math.h>

// ---------------------------------------------------------------------------
// Problem constants
// ---------------------------------------------------------------------------
#define NNODES   50000
#define NEDGES   800000
#define IN_DIM   128
#define HIDDEN   64
#define HEADS    4
#define NGRAPHS  256
#define HC1      256
#define NEG_SLOPE 0.2f

// ---------------------------------------------------------------------------
// Device scratch
// ---------------------------------------------------------------------------
__device__ __nv_bfloat16 g_hw[(size_t)NNODES * HC1];   // GEMM output (bf16)
__device__ float g_feat[(size_t)NNODES * HC1];          // aggregated output (fp32)
__device__ float g_alo[NNODES * HEADS];
__device__ float g_ahi[NNODES * HEADS];
__device__ int   g_off[NNODES + 1];
__device__ int   g_fill[NNODES];
__device__ int   g_csr[NEDGES];
__device__ float g_pool[NGRAPHS * HIDDEN];
__device__ float g_cnt[NGRAPHS];

// ---------------------------------------------------------------------------
// CSR build
// ---------------------------------------------------------------------------
__global__ void k_zero_csr() {
    int i = blockIdx.x * blockDim.x + threadIdx.x;
    if (i <= NNODES) g_off[i] = 0;
    if (i < NGRAPHS * HIDDEN) g_pool[i] = 0.f;
    if (i < NGRAPHS) g_cnt[i] = 0.f;
}

__global__ void k_hist(const int* __restrict__ dst) {
    int e = blockIdx.x * blockDim.x + threadIdx.x;
    if (e < NEDGES) atomicAdd(&g_off[dst[e] + 1], 1);
}

// single-block scan (warp-shuffle based); also writes g_fill[i] = exclusive
__global__ void k_scan() {
    __shared__ int wsum[32];
    __shared__ int carry;
    int t = threadIdx.x, lane = t & 31, wid = t >> 5;
    if (t == 0) carry = 0;
    __syncthreads();
    for (int base = 0; base < NNODES; base += 1024) {
        int i = base + t;
        int cnt = (i < NNODES) ? g_off[i + 1] : 0;
        int v = cnt;
        #pragma unroll
        for (int off = 1; off < 32; off <<= 1) {
            int nb = __shfl_up_sync(0xffffffffu, v, off);
            if (lane >= off) v += nb;
        }
        if (lane == 31) wsum[wid] = v;
        __syncthreads();
        if (wid == 0) {
            int s = wsum[lane];
            #pragma unroll
            for (int off = 1; off < 32; off <<= 1) {
                int nb = __shfl_up_sync(0xffffffffu, s, off);
                if (lane >= off) s += nb;
            }
            wsum[lane] = s;
        }
        __syncthreads();
        int add = carry + (wid > 0 ? wsum[wid - 1] : 0);
        int inc = v + add;
        if (i < NNODES) { g_off[i + 1] = inc; g_fill[i] = inc - cnt; }
        __syncthreads();
        if (t == 0) carry += wsum[31];
        __syncthreads();
    }
}

__global__ void k_scatter(const int* __restrict__ src, const int* __restrict__ dst) {
    int e = blockIdx.x * blockDim.x + threadIdx.x;
    if (e < NEDGES) {
        int p = atomicAdd(&g_fill[dst[e]], 1);
        g_csr[p] = src[e];
    }
}

// ---------------------------------------------------------------------------
// bf16 3-split tensor-core GEMM + fused attention-coefficient epilogue.
// C (bf16) [M,Nn] = A[M,K] @ B[Nn,K]^T ; alo/ahi from fp32 accumulators.
// ---------------------------------------------------------------------------
__device__ __forceinline__ void mma_bf16(float* d, const unsigned int* a, const unsigned int* b) {
    asm volatile(
        "mma.sync.aligned.m16n8k16.row.col.f32.bf16.bf16.f32 "
        "{%0,%1,%2,%3}, {%4,%5,%6,%7}, {%8,%9}, {%0,%1,%2,%3};\n"
        : "+f"(d[0]), "+f"(d[1]), "+f"(d[2]), "+f"(d[3])
        : "r"(a[0]), "r"(a[1]), "r"(a[2]), "r"(a[3]), "r"(b[0]), "r"(b[1]));
}

__device__ __forceinline__ unsigned int pack_bf2(__nv_bfloat16 a, __nv_bfloat16 b) {
    __nv_bfloat162 t(a, b);
    return *(unsigned int*)&t;
}

#define GBM 128
#define GBN 64
#define GBK 16
#define WSTR 12

__global__ __launch_bounds__(256) void k_gemm_bf16(
    const float* __restrict__ A, const float* __restrict__ B,
    __nv_bfloat16* __restrict__ C, int M, int Nn, int K,
    const float* __restrict__ a_src, const float* __restrict__ a_dst,
    float* __restrict__ alo, float* __restrict__ ahi, int H) {
    __shared__ unsigned int sAh[GBM * WSTR], sAl[GBM * WSTR];
    __shared__ unsigned int sBh[GBN * WSTR], sBl[GBN * WSTR];
    __shared__ float s_alo[GBM], s_ahi[GBM];

    int t = threadIdx.x;
    int lane = t & 31, warp = t >> 5;
    int wm = warp >> 1, wn = warp & 1;
    int m0 = blockIdx.y * GBM, n0 = blockIdx.x * GBN;
    int head = blockIdx.x;

    if (t < GBM) { s_alo[t] = 0.f; s_ahi[t] = 0.f; }

    float acc[2][4][4];
    #pragma unroll
    for (int i = 0; i < 2; i++)
        #pragma unroll
        for (int j = 0; j < 4; j++)
            #pragma unroll
            for (int k = 0; k < 4; k++) acc[i][j][k] = 0.f;

    for (int k0 = 0; k0 < K; k0 += GBK) {
        #pragma unroll
        for (int i = 0; i < 2; i++) {
            int lin = t + i * 256;
            int row = lin >> 2, c4 = (lin & 3) * 4;
            float4 v = make_float4(0.f, 0.f, 0.f, 0.f);
            int gm = m0 + row;
            if (gm < M) v = *(const float4*)&A[(size_t)gm * K + k0 + c4];
            __nv_bfloat16 hx = __float2bfloat16(v.x), hy = __float2bfloat16(v.y);
            __nv_bfloat16 hz = __float2bfloat16(v.z), hw4 = __float2bfloat16(v.w);
            __nv_bfloat16 lx = __float2bfloat16(v.x - __bfloat162float(hx));
            __nv_bfloat16 ly = __float2bfloat16(v.y - __bfloat162float(hy));
            __nv_bfloat16 lz = __float2bfloat16(v.z - __bfloat162float(hz));
            __nv_bfloat16 lw = __float2bfloat16(v.w - __bfloat162float(hw4));
            int w0 = row * WSTR + (c4 >> 1);
            sAh[w0] = pack_bf2(hx, hy); sAh[w0 + 1] = pack_bf2(hz, hw4);
            sAl[w0] = pack_bf2(lx, ly); sAl[w0 + 1] = pack_bf2(lz, lw);
        }
        {
            int row = t >> 2, c4 = (t & 3) * 4;
            float4 v = *(const float4*)&B[(size_t)(n0 + row) * K + k0 + c4];
            __nv_bfloat16 hx = __float2bfloat16(v.x), hy = __float2bfloat16(v.y);
            __nv_bfloat16 hz = __float2bfloat16(v.z), hw4 = __float2bfloat16(v.w);
            __nv_bfloat16 lx = __float2bfloat16(v.x - __bfloat162float(hx));
            __nv_bfloat16 ly = __float2bfloat16(v.y - __bfloat162float(hy));
            __nv_bfloat16 lz = __float2bfloat16(v.z - __bfloat162float(hz));
            __nv_bfloat16 lw = __float2bfloat16(v.w - __bfloat162float(hw4));
            int w0 = row * WSTR + (c4 >> 1);
            sBh[w0] = pack_bf2(hx, hy); sBh[w0 + 1] = pack_bf2(hz, hw4);
            sBl[w0] = pack_bf2(lx, ly); sBl[w0 + 1] = pack_bf2(lz, lw);
        }
        __syncthreads();

        unsigned int ah[2][4], al[2][4];
        #pragma unroll
        for (int mi = 0; mi < 2; mi++) {
            int r = wm * 32 + mi * 16 + (lane >> 2);
            int c = lane & 3;
            ah[mi][0] = sAh[r * WSTR + c];
            ah[mi][1] = sAh[(r + 8) * WSTR + c];
            ah[mi][2] = sAh[r * WSTR + c + 4];
            ah[mi][3] = sAh[(r + 8) * WSTR + c + 4];
            al[mi][0] = sAl[r * WSTR + c];
            al[mi][1] = sAl[(r + 8) * WSTR + c];
            al[mi][2] = sAl[r * WSTR + c + 4];
            al[mi][3] = sAl[(r + 8) * WSTR + c + 4];
        }
        unsigned int bh[4][2], bl[4][2];
        #pragma unroll
        for (int ni = 0; ni < 4; ni++) {
            int n = wn * 32 + ni * 8 + (lane >> 2);
            int c = lane & 3;
            bh[ni][0] = sBh[n * WSTR + c];
            bh[ni][1] = sBh[n * WSTR + c + 4];
            bl[ni][0] = sBl[n * WSTR + c];
            bl[ni][1] = sBl[n * WSTR + c + 4];
        }
        #pragma unroll
        for (int mi = 0; mi < 2; mi++)
            #pragma unroll
            for (int ni = 0; ni < 4; ni++) {
                mma_bf16(acc[mi][ni], ah[mi], bh[ni]);
                mma_bf16(acc[mi][ni], ah[mi], bl[ni]);
                mma_bf16(acc[mi][ni], al[mi], bh[ni]);
            }
        __syncthreads();
    }

    // ---- epilogue: bf16 C store + fused alo/ahi ----
    const float* as_h = a_src + head * 64;
    const float* ad_h = a_dst + head * 64;
    float sl[4] = {0.f, 0.f, 0.f, 0.f};
    float sh_[4] = {0.f, 0.f, 0.f, 0.f};

    #pragma unroll
    for (int mi = 0; mi < 2; mi++) {
        int r0 = m0 + wm * 32 + mi * 16 + (lane >> 2);
        #pragma unroll
        for (int ni = 0; ni < 4; ni++) {
            int cl = wn * 32 + ni * 8 + (lane & 3) * 2;
            float as0 = as_h[cl], as1 = as_h[cl + 1];
            float ad0 = ad_h[cl], ad1 = ad_h[cl + 1];
            sl[mi * 2 + 0] += acc[mi][ni][0] * as0 + acc[mi][ni][1] * as1;
            sh_[mi * 2 + 0] += acc[mi][ni][0] * ad0 + acc[mi][ni][1] * ad1;
            sl[mi * 2 + 1] += acc[mi][ni][2] * as0 + acc[mi][ni][3] * as1;
            sh_[mi * 2 + 1] += acc[mi][ni][2] * ad0 + acc[mi][ni][3] * ad1;
            int c = n0 + cl;
            if (r0 < M) {
                __nv_bfloat162 p(__float2bfloat16(acc[mi][ni][0]), __float2bfloat16(acc[mi][ni][1]));
                *(__nv_bfloat162*)&C[(size_t)r0 * Nn + c] = p;
            }
            if (r0 + 8 < M) {
                __nv_bfloat162 p(__float2bfloat16(acc[mi][ni][2]), __float2bfloat16(acc[mi][ni][3]));
                *(__nv_bfloat162*)&C[(size_t)(r0 + 8) * Nn + c] = p;
            }
        }
    }
    #pragma unroll
    for (int off = 1; off <= 2; off <<= 1)
        #pragma unroll
        for (int i = 0; i < 4; i++) {
            sl[i] += __shfl_xor_sync(0xffffffffu, sl[i], off);
            sh_[i] += __shfl_xor_sync(0xffffffffu, sh_[i], off);
        }
    if ((lane & 3) == 0) {
        #pragma unroll
        for (int mi = 0; mi < 2; mi++) {
            int rl = wm * 32 + mi * 16 + (lane >> 2);
            atomicAdd(&s_alo[rl], sl[mi * 2]);
            atomicAdd(&s_ahi[rl], sh_[mi * 2]);
            atomicAdd(&s_alo[rl + 8], sl[mi * 2 + 1]);
            atomicAdd(&s_ahi[rl + 8], sh_[mi * 2 + 1]);
        }
    }
    __syncthreads();
    if (t < GBM && m0 + t < M) {
        alo[(m0 + t) * H + head] = s_alo[t];
        ahi[(m0 + t) * H + head] = s_ahi[t];
    }
}

// ---------------------------------------------------------------------------
// Aggregation (layers 1/2, H=4): bf16 gather, online softmax, fp32 out.
// ---------------------------------------------------------------------------
__device__ __forceinline__ float lrelu(float x) { return x > 0.f ? x : NEG_SLOPE * x; }

__global__ void k_aggregate4(const __nv_bfloat16* __restrict__ hw,
                             const float* __restrict__ alo,
                             const float* __restrict__ ahi,
                             const float* __restrict__ bias,
                             float* __restrict__ out) {
    const int H = 4, HCn = 256, FPL = 8, LPH = 8;
    int warp = (blockIdx.x * blockDim.x + threadIdx.x) >> 5;
    int lane = threadIdx.x & 31;
    if (warp >= NNODES) return;
    int n = warp;
    int beg = g_off[n], deg = g_off[n + 1] - beg;

    float ahin[H];
    #pragma unroll
    for (int hh = 0; hh < H; hh++) ahin[hh] = ahi[n * H + hh];

    float mx[H], den[H];
    #pragma unroll
    for (int hh = 0; hh < H; hh++) { mx[hh] = -1e30f; den[hh] = 0.f; }
    for (int j = lane; j <= deg; j += 32) {
        int src = (j < deg) ? g_csr[beg + j] : n;
        #pragma unroll
        for (int hh = 0; hh < H; hh++) {
            float e = lrelu(alo[src * H + hh] + ahin[hh]);
            float mn = fmaxf(mx[hh], e);
            den[hh] = den[hh] * __expf(mx[hh] - mn) + __expf(e - mn);
            mx[hh] = mn;
        }
    }
    #pragma unroll
    for (int off = 16; off > 0; off >>= 1)
        #pragma unroll
        for (int hh = 0; hh < H; hh++) {
            float mo = __shfl_xor_sync(0xffffffffu, mx[hh], off);
            float doo = __shfl_xor_sync(0xffffffffu, den[hh], off);
            float mn = fmaxf(mx[hh], mo);
            den[hh] = den[hh] * __expf(mx[hh] - mn) + doo * __expf(mo - mn);
            mx[hh] = mn;
        }

    int hh_l = lane / LPH;
    float my_m = 0.f, my_d = 0.f, my_a = 0.f;
    #pragma unroll
    for (int hh = 0; hh < H; hh++)
        if (hh == hh_l) { my_m = mx[hh]; my_d = den[hh]; my_a = ahin[hh]; }
    float inv_d = 1.f / (my_d + 1e-16f);

    float acc[FPL];
    #pragma unroll
    for (int i = 0; i < FPL; i++) acc[i] = 0.f;
    for (int j = 0; j <= deg; j++) {
        int src = (j < deg) ? g_csr[beg + j] : n;
        float e = lrelu(alo[src * H + hh_l] + my_a);
        float w = __expf(e - my_m) * inv_d;
        const uint4* hp = (const uint4*)(hw + (size_t)src * HCn + lane * FPL);
        uint4 r = *hp;
        float2 f0 = __bfloat1622float2(*(__nv_bfloat162*)&r.x);
        float2 f1 = __bfloat1622float2(*(__nv_bfloat162*)&r.y);
        float2 f2 = __bfloat1622float2(*(__nv_bfloat162*)&r.z);
        float2 f3 = __bfloat1622float2(*(__nv_bfloat162*)&r.w);
        acc[0] += w * f0.x; acc[1] += w * f0.y;
        acc[2] += w * f1.x; acc[3] += w * f1.y;
        acc[4] += w * f2.x; acc[5] += w * f2.y;
        acc[6] += w * f3.x; acc[7] += w * f3.y;
    }
    #pragma unroll
    for (int i = 0; i < FPL; i++) {
        float v = acc[i] + bias[lane * FPL + i];
        v = (v > 0.f) ? v : (expm1f(v));
        out[(size_t)n * HCn + lane * FPL + i] = v;
    }
}

// ---------------------------------------------------------------------------
// Layer-3 aggregation (H=1) fused with mean-pool accumulation.
// ---------------------------------------------------------------------------
__global__ void k_aggregate1_pool(const __nv_bfloat16* __restrict__ hw,
                                  const float* __restrict__ alo,
                                  const float* __restrict__ ahi,
                                  const float* __restrict__ bias,
                                  const int* __restrict__ batch) {
    const int HCn = 64, FPL = 2;
    int warp = (blockIdx.x * blockDim.x + threadIdx.x) >> 5;
    int lane = threadIdx.x & 31;
    if (warp >= NNODES) return;
    int n = warp;
    int beg = g_off[n], deg = g_off[n + 1] - beg;

    float ahin = ahi[n];
    float mx = -1e30f, den = 0.f;
    for (int j = lane; j <= deg; j += 32) {
        int src = (j < deg) ? g_csr[beg + j] : n;
        float e = lrelu(alo[src] + ahin);
        float mn = fmaxf(mx, e);
        den = den * __expf(mx - mn) + __expf(e - mn);
        mx = mn;
    }
    #pragma unroll
    for (int off = 16; off > 0; off >>= 1) {
        float mo = __shfl_xor_sync(0xffffffffu, mx, off);
        float doo = __shfl_xor_sync(0xffffffffu, den, off);
        float mn = fmaxf(mx, mo);
        den = den * __expf(mx - mn) + doo * __expf(mo - mn);
        mx = mn;
    }
    float inv_d = 1.f / (den + 1e-16f);

    float a0 = 0.f, a1 = 0.f;
    for (int j = 0; j <= deg; j++) {
        int src = (j < deg) ? g_csr[beg + j] : n;
        float e = lrelu(alo[src] + ahin);
        float w = __expf(e - mx) * inv_d;
        unsigned int r = *(const unsigned int*)(hw + (size_t)src * HCn + lane * FPL);
        float2 f = __bfloat1622float2(*(__nv_bfloat162*)&r);
        a0 += w * f.x; a1 += w * f.y;
    }
    float v0 = a0 + bias[lane * FPL];
    float v1 = a1 + bias[lane * FPL + 1];
    v0 = (v0 > 0.f) ? v0 : expm1f(v0);
    v1 = (v1 > 0.f) ? v1 : expm1f(v1);

    int b = batch[n];
    atomicAdd(&g_pool[b * HIDDEN + lane * FPL], v0);
    atomicAdd(&g_pool[b * HIDDEN + lane * FPL + 1], v1);
    if (lane == 0) atomicAdd(&g_cnt[b], 1.f);
}

// ---------------------------------------------------------------------------
// Heads MLP: one warp per graph
// ---------------------------------------------------------------------------
__global__ void k_mlp(const float* __restrict__ Wc1, const float* __restrict__ bc1,
                      const float* __restrict__ Wc2, const float* __restrict__ bc2,
                      const float* __restrict__ Wr1, const float* __restrict__ br1,
                      const float* __restrict__ Wr2, const float* __restrict__ br2,
                      float* __restrict__ out) {
    int warp = (blockIdx.x * blockDim.x + threadIdx.x) >> 5;
    int lane = threadIdx.x & 31;
    if (warp >= NGRAPHS) return;
    float inv_cnt = 1.f / fmaxf(g_cnt[warp], 1.f);
    const float* gp = &g_pool[warp * HIDDEN];

    {
        float h0 = bc1[lane], h1 = bc1[lane + 32];
        for (int c = 0; c < HIDDEN; c++) {
            float gc = gp[c] * inv_cnt;
            h0 += Wc1[lane * HIDDEN + c] * gc;
            h1 += Wc1[(lane + 32) * HIDDEN + c] * gc;
        }
        h0 = fmaxf(h0, 0.f); h1 = fmaxf(h1, 0.f);
        float s = Wc2[lane] * h0 + Wc2[lane + 32] * h1;
        #pragma unroll
        for (int off = 16; off > 0; off >>= 1) s += __shfl_xor_sync(0xffffffffu, s, off);
        if (lane == 0) out[warp] = s + bc2[0];
    }
    {
        float h0 = br1[lane], h1 = br1[lane + 32];
        for (int c = 0; c < HIDDEN; c++) {
            float gc = gp[c] * inv_cnt;
            h0 += Wr1[lane * HIDDEN + c] * gc;
            h1 += Wr1[(lane + 32) * HIDDEN + c] * gc;
        }
        h0 = fmaxf(h0, 0.f); h1 = fmaxf(h1, 0.f);
        float s = Wr2[lane] * h0 + Wr2[lane + 32] * h1;
        #pragma unroll
        for (int off = 16; off > 0; off >>= 1) s += __shfl_xor_sync(0xffffffffu, s, off);
        if (lane == 0) out[NGRAPHS + warp] = s + br2[0];
    }
}

// ---------------------------------------------------------------------------
// Launch
// ---------------------------------------------------------------------------
extern "C" void kernel_launch(void* const* d_in, const int* in_sizes, int n_in,
                              void* d_out, int out_size) {
    const float* x     = (const float*)d_in[0];
    const int*   ei    = (const int*)d_in[1];
    const int*   batch = (const int*)d_in[2];
    const float* W1  = (const float*)d_in[3];
    const float* as1 = (const float*)d_in[4];
    const float* ad1 = (const float*)d_in[5];
    const float* b1  = (const float*)d_in[6];
    const float* W2  = (const float*)d_in[7];
    const float* as2 = (const float*)d_in[8];
    const float* ad2 = (const float*)d_in[9];
    const float* b2  = (const float*)d_in[10];
    const float* W3  = (const float*)d_in[11];
    const float* as3 = (const float*)d_in[12];
    const float* ad3 = (const float*)d_in[13];
    const float* b3  = (const float*)d_in[14];
    const float* Wc1 = (const float*)d_in[15];
    const float* bc1 = (const float*)d_in[16];
    const float* Wc2 = (const float*)d_in[17];
    const float* bc2 = (const float*)d_in[18];
    const float* Wr1 = (const float*)d_in[19];
    const float* br1 = (const float*)d_in[20];
    const float* Wr2 = (const float*)d_in[21];
    const float* br2 = (const float*)d_in[22];
    float* out = (float*)d_out;

    const int* srcp = ei;
    const int* dstp = ei + NEDGES;

    k_zero_csr<<<(NNODES + 256) / 256, 256>>>();
    k_hist<<<(NEDGES + 255) / 256, 256>>>(dstp);
    k_scan<<<1, 1024>>>();
    k_scatter<<<(NEDGES + 255) / 256, 256>>>(srcp, dstp);

    __nv_bfloat16* hw_p = nullptr; cudaGetSymbolAddress((void**)&hw_p, g_hw);
    float* feat_p = nullptr; cudaGetSymbolAddress((void**)&feat_p, g_feat);
    float* alo_p  = nullptr; cudaGetSymbolAddress((void**)&alo_p,  g_alo);
    float* ahi_p  = nullptr; cudaGetSymbolAddress((void**)&ahi_p,  g_ahi);

    const int warps_grid = (NNODES * 32 + 255) / 256;
    const int mblocks = (NNODES + GBM - 1) / GBM;

    // Layer 1
    {
        dim3 grid(HC1 / GBN, mblocks);
        k_gemm_bf16<<<grid, 256>>>(x, W1, hw_p, NNODES, HC1, IN_DIM, as1, ad1, alo_p, ahi_p, HEADS);
        k_aggregate4<<<warps_grid, 256>>>(hw_p, alo_p, ahi_p, b1, feat_p);
    }
    // Layer 2
    {
        dim3 grid(HC1 / GBN, mblocks);
        k_gemm_bf16<<<grid, 256>>>(feat_p, W2, hw_p, NNODES, HC1, HC1, as2, ad2, alo_p, ahi_p, HEADS);
        k_aggregate4<<<warps_grid, 256>>>(hw_p, alo_p, ahi_p, b2, feat_p);
    }
    // Layer 3 (heads=1) fused with pool
    {
        dim3 grid(HIDDEN / GBN, mblocks);
        k_gemm_bf16<<<grid, 256>>>(feat_p, W3, hw_p, NNODES, HIDDEN, HC1, as3, ad3, alo_p, ahi_p, 1);
        k_aggregate1_pool<<<warps_grid, 256>>>(hw_p, alo_p, ahi_p, b3, batch);
    }

    k_mlp<<<(NGRAPHS * 32 + 255) / 256, 256>>>(Wc1, bc1, Wc2, bc2, Wr1, br1, Wr2, br2, out);
}

// round 6
// speedup vs baseline: 2.3019x; 1.0200x over previous
#include <cuda_runtime.h>
#include <cuda_bf16.h>
#include <stdint.h>
#include <math.h>

// ---------------------------------------------------------------------------
// Problem constants
// ---------------------------------------------------------------------------
#define NNODES   50000
#define NEDGES   800000
#define IN_DIM   128
#define HIDDEN   64
#define HEADS    4
#define NGRAPHS  256
#define HC1      256
#define NEG_SLOPE 0.2f

// ---------------------------------------------------------------------------
// Device scratch
// ---------------------------------------------------------------------------
__device__ __nv_bfloat16 g_hw[(size_t)NNODES * HC1];
__device__ float g_feat[(size_t)NNODES * HC1];
__device__ float g_alo[NNODES * HEADS];
__device__ float g_ahi[NNODES * HEADS];
__device__ int   g_off[NNODES + 1];
__device__ int   g_fill[NNODES];
__device__ int   g_csr[NEDGES];
__device__ float g_pool[NGRAPHS * HIDDEN];
__device__ float g_cnt[NGRAPHS];

// ---------------------------------------------------------------------------
// CSR build
// ---------------------------------------------------------------------------
__global__ void k_zero_csr() {
    int i = blockIdx.x * blockDim.x + threadIdx.x;
    if (i <= NNODES) g_off[i] = 0;
    if (i < NGRAPHS * HIDDEN) g_pool[i] = 0.f;
    if (i < NGRAPHS) g_cnt[i] = 0.f;
}

__global__ void k_hist(const int* __restrict__ dst) {
    int e = blockIdx.x * blockDim.x + threadIdx.x;
    if (e < NEDGES) atomicAdd(&g_off[dst[e] + 1], 1);
}

__global__ void k_scan() {
    __shared__ int wsum[32];
    __shared__ int carry;
    int t = threadIdx.x, lane = t & 31, wid = t >> 5;
    if (t == 0) carry = 0;
    __syncthreads();
    for (int base = 0; base < NNODES; base += 1024) {
        int i = base + t;
        int cnt = (i < NNODES) ? g_off[i + 1] : 0;
        int v = cnt;
        #pragma unroll
        for (int off = 1; off < 32; off <<= 1) {
            int nb = __shfl_up_sync(0xffffffffu, v, off);
            if (lane >= off) v += nb;
        }
        if (lane == 31) wsum[wid] = v;
        __syncthreads();
        if (wid == 0) {
            int s = wsum[lane];
            #pragma unroll
            for (int off = 1; off < 32; off <<= 1) {
                int nb = __shfl_up_sync(0xffffffffu, s, off);
                if (lane >= off) s += nb;
            }
            wsum[lane] = s;
        }
        __syncthreads();
        int add = carry + (wid > 0 ? wsum[wid - 1] : 0);
        int inc = v + add;
        if (i < NNODES) { g_off[i + 1] = inc; g_fill[i] = inc - cnt; }
        __syncthreads();
        if (t == 0) carry += wsum[31];
        __syncthreads();
    }
}

__global__ void k_scatter(const int* __restrict__ src, const int* __restrict__ dst) {
    int e = blockIdx.x * blockDim.x + threadIdx.x;
    if (e < NEDGES) {
        int p = atomicAdd(&g_fill[dst[e]], 1);
        g_csr[p] = src[e];
    }
}

// ---------------------------------------------------------------------------
// bf16 3-split tensor-core GEMM, software-pipelined (register prefetch),
// + fused attention-coefficient epilogue.
// ---------------------------------------------------------------------------
__device__ __forceinline__ void mma_bf16(float* d, const unsigned int* a, const unsigned int* b) {
    asm volatile(
        "mma.sync.aligned.m16n8k16.row.col.f32.bf16.bf16.f32 "
        "{%0,%1,%2,%3}, {%4,%5,%6,%7}, {%8,%9}, {%0,%1,%2,%3};\n"
        : "+f"(d[0]), "+f"(d[1]), "+f"(d[2]), "+f"(d[3])
        : "r"(a[0]), "r"(a[1]), "r"(a[2]), "r"(a[3]), "r"(b[0]), "r"(b[1]));
}

__device__ __forceinline__ unsigned int pack_bf2(__nv_bfloat16 a, __nv_bfloat16 b) {
    __nv_bfloat162 t(a, b);
    return *(unsigned int*)&t;
}

#define GBM 128
#define GBN 64
#define GBK 16
#define WSTR 12

__global__ __launch_bounds__(256) void k_gemm_bf16(
    const float* __restrict__ A, const float* __restrict__ B,
    __nv_bfloat16* __restrict__ C, int M, int Nn, int K,
    const float* __restrict__ a_src, const float* __restrict__ a_dst,
    float* __restrict__ alo, float* __restrict__ ahi, int H) {
    __shared__ unsigned int sAh[GBM * WSTR], sAl[GBM * WSTR];
    __shared__ unsigned int sBh[GBN * WSTR], sBl[GBN * WSTR];
    __shared__ float s_alo[GBM], s_ahi[GBM];

    int t = threadIdx.x;
    int lane = t & 31, warp = t >> 5;
    int wm = warp >> 1, wn = warp & 1;
    int m0 = blockIdx.y * GBM, n0 = blockIdx.x * GBN;
    int head = blockIdx.x;

    if (t < GBM) { s_alo[t] = 0.f; s_ahi[t] = 0.f; }

    // load-index precompute
    int arow0 = t >> 2,         ac4 = (t & 3) * 4;
    int arow1 = (t + 256) >> 2; // second A chunk
    int brow = t >> 2,          bc4 = (t & 3) * 4;
    int gmA0 = m0 + arow0, gmA1 = m0 + arow1;
    const float* pA0 = A + (size_t)gmA0 * K + ac4;
    const float* pA1 = A + (size_t)gmA1 * K + ac4;
    const float* pB  = B + (size_t)(n0 + brow) * K + bc4;
    bool vA0 = gmA0 < M, vA1 = gmA1 < M;

    float acc[2][4][4];
    #pragma unroll
    for (int i = 0; i < 2; i++)
        #pragma unroll
        for (int j = 0; j < 4; j++)
            #pragma unroll
            for (int k = 0; k < 4; k++) acc[i][j][k] = 0.f;

    // initial prefetch (k0 = 0)
    float4 pa0 = vA0 ? *(const float4*)pA0 : make_float4(0.f,0.f,0.f,0.f);
    float4 pa1 = vA1 ? *(const float4*)pA1 : make_float4(0.f,0.f,0.f,0.f);
    float4 pb  = *(const float4*)pB;

    for (int k0 = 0; k0 < K; k0 += GBK) {
        // convert prefetched registers -> smem split tiles
        {
            float4 v = pa0;
            __nv_bfloat16 hx = __float2bfloat16(v.x), hy = __float2bfloat16(v.y);
            __nv_bfloat16 hz = __float2bfloat16(v.z), hw4 = __float2bfloat16(v.w);
            __nv_bfloat16 lx = __float2bfloat16(v.x - __bfloat162float(hx));
            __nv_bfloat16 ly = __float2bfloat16(v.y - __bfloat162float(hy));
            __nv_bfloat16 lz = __float2bfloat16(v.z - __bfloat162float(hz));
            __nv_bfloat16 lw = __float2bfloat16(v.w - __bfloat162float(hw4));
            int w0 = arow0 * WSTR + (ac4 >> 1);
            sAh[w0] = pack_bf2(hx, hy); sAh[w0 + 1] = pack_bf2(hz, hw4);
            sAl[w0] = pack_bf2(lx, ly); sAl[w0 + 1] = pack_bf2(lz, lw);
        }
        {
            float4 v = pa1;
            __nv_bfloat16 hx = __float2bfloat16(v.x), hy = __float2bfloat16(v.y);
            __nv_bfloat16 hz = __float2bfloat16(v.z), hw4 = __float2bfloat16(v.w);
            __nv_bfloat16 lx = __float2bfloat16(v.x - __bfloat162float(hx));
            __nv_bfloat16 ly = __float2bfloat16(v.y - __bfloat162float(hy));
            __nv_bfloat16 lz = __float2bfloat16(v.z - __bfloat162float(hz));
            __nv_bfloat16 lw = __float2bfloat16(v.w - __bfloat162float(hw4));
            int w0 = arow1 * WSTR + (ac4 >> 1);
            sAh[w0] = pack_bf2(hx, hy); sAh[w0 + 1] = pack_bf2(hz, hw4);
            sAl[w0] = pack_bf2(lx, ly); sAl[w0 + 1] = pack_bf2(lz, lw);
        }
        {
            float4 v = pb;
            __nv_bfloat16 hx = __float2bfloat16(v.x), hy = __float2bfloat16(v.y);
            __nv_bfloat16 hz = __float2bfloat16(v.z), hw4 = __float2bfloat16(v.w);
            __nv_bfloat16 lx = __float2bfloat16(v.x - __bfloat162float(hx));
            __nv_bfloat16 ly = __float2bfloat16(v.y - __bfloat162float(hy));
            __nv_bfloat16 lz = __float2bfloat16(v.z - __bfloat162float(hz));
            __nv_bfloat16 lw = __float2bfloat16(v.w - __bfloat162float(hw4));
            int w0 = brow * WSTR + (bc4 >> 1);
            sBh[w0] = pack_bf2(hx, hy); sBh[w0 + 1] = pack_bf2(hz, hw4);
            sBl[w0] = pack_bf2(lx, ly); sBl[w0 + 1] = pack_bf2(lz, lw);
        }
        __syncthreads();

        // issue next prefetch — LDGs overlap the MMA section below
        if (k0 + GBK < K) {
            pa0 = vA0 ? *(const float4*)(pA0 + k0 + GBK) : make_float4(0.f,0.f,0.f,0.f);
            pa1 = vA1 ? *(const float4*)(pA1 + k0 + GBK) : make_float4(0.f,0.f,0.f,0.f);
            pb  = *(const float4*)(pB + k0 + GBK);
        }

        unsigned int ah[2][4], al[2][4];
        #pragma unroll
        for (int mi = 0; mi < 2; mi++) {
            int r = wm * 32 + mi * 16 + (lane >> 2);
            int c = lane & 3;
            ah[mi][0] = sAh[r * WSTR + c];
            ah[mi][1] = sAh[(r + 8) * WSTR + c];
            ah[mi][2] = sAh[r * WSTR + c + 4];
            ah[mi][3] = sAh[(r + 8) * WSTR + c + 4];
            al[mi][0] = sAl[r * WSTR + c];
            al[mi][1] = sAl[(r + 8) * WSTR + c];
            al[mi][2] = sAl[r * WSTR + c + 4];
            al[mi][3] = sAl[(r + 8) * WSTR + c + 4];
        }
        unsigned int bh[4][2], bl[4][2];
        #pragma unroll
        for (int ni = 0; ni < 4; ni++) {
            int n = wn * 32 + ni * 8 + (lane >> 2);
            int c = lane & 3;
            bh[ni][0] = sBh[n * WSTR + c];
            bh[ni][1] = sBh[n * WSTR + c + 4];
            bl[ni][0] = sBl[n * WSTR + c];
            bl[ni][1] = sBl[n * WSTR + c + 4];
        }
        #pragma unroll
        for (int mi = 0; mi < 2; mi++)
            #pragma unroll
            for (int ni = 0; ni < 4; ni++) {
                mma_bf16(acc[mi][ni], ah[mi], bh[ni]);
                mma_bf16(acc[mi][ni], ah[mi], bl[ni]);
                mma_bf16(acc[mi][ni], al[mi], bh[ni]);
            }
        __syncthreads();
    }

    // ---- epilogue: bf16 C store + fused alo/ahi ----
    const float* as_h = a_src + head * 64;
    const float* ad_h = a_dst + head * 64;
    float sl[4] = {0.f, 0.f, 0.f, 0.f};
    float sh_[4] = {0.f, 0.f, 0.f, 0.f};

    #pragma unroll
    for (int mi = 0; mi < 2; mi++) {
        int r0 = m0 + wm * 32 + mi * 16 + (lane >> 2);
        #pragma unroll
        for (int ni = 0; ni < 4; ni++) {
            int cl = wn * 32 + ni * 8 + (lane & 3) * 2;
            float as0 = as_h[cl], as1 = as_h[cl + 1];
            float ad0 = ad_h[cl], ad1 = ad_h[cl + 1];
            sl[mi * 2 + 0] += acc[mi][ni][0] * as0 + acc[mi][ni][1] * as1;
            sh_[mi * 2 + 0] += acc[mi][ni][0] * ad0 + acc[mi][ni][1] * ad1;
            sl[mi * 2 + 1] += acc[mi][ni][2] * as0 + acc[mi][ni][3] * as1;
            sh_[mi * 2 + 1] += acc[mi][ni][2] * ad0 + acc[mi][ni][3] * ad1;
            int c = n0 + cl;
            if (r0 < M) {
                __nv_bfloat162 p(__float2bfloat16(acc[mi][ni][0]), __float2bfloat16(acc[mi][ni][1]));
                *(__nv_bfloat162*)&C[(size_t)r0 * Nn + c] = p;
            }
            if (r0 + 8 < M) {
                __nv_bfloat162 p(__float2bfloat16(acc[mi][ni][2]), __float2bfloat16(acc[mi][ni][3]));
                *(__nv_bfloat162*)&C[(size_t)(r0 + 8) * Nn + c] = p;
            }
        }
    }
    #pragma unroll
    for (int off = 1; off <= 2; off <<= 1)
        #pragma unroll
        for (int i = 0; i < 4; i++) {
            sl[i] += __shfl_xor_sync(0xffffffffu, sl[i], off);
            sh_[i] += __shfl_xor_sync(0xffffffffu, sh_[i], off);
        }
    if ((lane & 3) == 0) {
        #pragma unroll
        for (int mi = 0; mi < 2; mi++) {
            int rl = wm * 32 + mi * 16 + (lane >> 2);
            atomicAdd(&s_alo[rl], sl[mi * 2]);
            atomicAdd(&s_ahi[rl], sh_[mi * 2]);
            atomicAdd(&s_alo[rl + 8], sl[mi * 2 + 1]);
            atomicAdd(&s_ahi[rl + 8], sh_[mi * 2 + 1]);
        }
    }
    __syncthreads();
    if (t < GBM && m0 + t < M) {
        alo[(m0 + t) * H + head] = s_alo[t];
        ahi[(m0 + t) * H + head] = s_ahi[t];
    }
}

// ---------------------------------------------------------------------------
// Aggregation (layers 1/2, H=4): bf16 gather, online softmax, fp32 out.
// Pass-3 unrolled x2 for MLP.
// ---------------------------------------------------------------------------
__device__ __forceinline__ float lrelu(float x) { return x > 0.f ? x : NEG_SLOPE * x; }

__global__ void k_aggregate4(const __nv_bfloat16* __restrict__ hw,
                             const float* __restrict__ alo,
                             const float* __restrict__ ahi,
                             const float* __restrict__ bias,
                             float* __restrict__ out) {
    const int H = 4, HCn = 256, FPL = 8, LPH = 8;
    int warp = (blockIdx.x * blockDim.x + threadIdx.x) >> 5;
    int lane = threadIdx.x & 31;
    if (warp >= NNODES) return;
    int n = warp;
    int beg = g_off[n], deg = g_off[n + 1] - beg;

    float ahin[H];
    #pragma unroll
    for (int hh = 0; hh < H; hh++) ahin[hh] = ahi[n * H + hh];

    float mx[H], den[H];
    #pragma unroll
    for (int hh = 0; hh < H; hh++) { mx[hh] = -1e30f; den[hh] = 0.f; }
    for (int j = lane; j <= deg; j += 32) {
        int src = (j < deg) ? g_csr[beg + j] : n;
        #pragma unroll
        for (int hh = 0; hh < H; hh++) {
            float e = lrelu(alo[src * H + hh] + ahin[hh]);
            float mn = fmaxf(mx[hh], e);
            den[hh] = den[hh] * __expf(mx[hh] - mn) + __expf(e - mn);
            mx[hh] = mn;
        }
    }
    #pragma unroll
    for (int off = 16; off > 0; off >>= 1)
        #pragma unroll
        for (int hh = 0; hh < H; hh++) {
            float mo = __shfl_xor_sync(0xffffffffu, mx[hh], off);
            float doo = __shfl_xor_sync(0xffffffffu, den[hh], off);
            float mn = fmaxf(mx[hh], mo);
            den[hh] = den[hh] * __expf(mx[hh] - mn) + doo * __expf(mo - mn);
            mx[hh] = mn;
        }

    int hh_l = lane / LPH;
    float my_m = 0.f, my_d = 0.f, my_a = 0.f;
    #pragma unroll
    for (int hh = 0; hh < H; hh++)
        if (hh == hh_l) { my_m = mx[hh]; my_d = den[hh]; my_a = ahin[hh]; }
    float inv_d = 1.f / (my_d + 1e-16f);

    float acc[FPL];
    #pragma unroll
    for (int i = 0; i < FPL; i++) acc[i] = 0.f;

    const int total = deg + 1;   // incl. self loop at the end
    int j = 0;
    for (; j + 1 < total; j += 2) {
        int s0 = g_csr[beg + j];                         // j < deg guaranteed
        int s1 = (j + 1 < deg) ? g_csr[beg + j + 1] : n;
        uint4 r0 = *(const uint4*)(hw + (size_t)s0 * HCn + lane * FPL);
        uint4 r1 = *(const uint4*)(hw + (size_t)s1 * HCn + lane * FPL);
        float w0 = __expf(lrelu(alo[s0 * H + hh_l] + my_a) - my_m) * inv_d;
        float w1 = __expf(lrelu(alo[s1 * H + hh_l] + my_a) - my_m) * inv_d;
        float2 f;
        f = __bfloat1622float2(*(__nv_bfloat162*)&r0.x); acc[0] += w0 * f.x; acc[1] += w0 * f.y;
        f = __bfloat1622float2(*(__nv_bfloat162*)&r0.y); acc[2] += w0 * f.x; acc[3] += w0 * f.y;
        f = __bfloat1622float2(*(__nv_bfloat162*)&r0.z); acc[4] += w0 * f.x; acc[5] += w0 * f.y;
        f = __bfloat1622float2(*(__nv_bfloat162*)&r0.w); acc[6] += w0 * f.x; acc[7] += w0 * f.y;
        f = __bfloat1622float2(*(__nv_bfloat162*)&r1.x); acc[0] += w1 * f.x; acc[1] += w1 * f.y;
        f = __bfloat1622float2(*(__nv_bfloat162*)&r1.y); acc[2] += w1 * f.x; acc[3] += w1 * f.y;
        f = __bfloat1622float2(*(__nv_bfloat162*)&r1.z); acc[4] += w1 * f.x; acc[5] += w1 * f.y;
        f = __bfloat1622float2(*(__nv_bfloat162*)&r1.w); acc[6] += w1 * f.x; acc[7] += w1 * f.y;
    }
    if (j < total) {
        int s = (j < deg) ? g_csr[beg + j] : n;
        uint4 r = *(const uint4*)(hw + (size_t)s * HCn + lane * FPL);
        float w = __expf(lrelu(alo[s * H + hh_l] + my_a) - my_m) * inv_d;
        float2 f;
        f = __bfloat1622float2(*(__nv_bfloat162*)&r.x); acc[0] += w * f.x; acc[1] += w * f.y;
        f = __bfloat1622float2(*(__nv_bfloat162*)&r.y); acc[2] += w * f.x; acc[3] += w * f.y;
        f = __bfloat1622float2(*(__nv_bfloat162*)&r.z); acc[4] += w * f.x; acc[5] += w * f.y;
        f = __bfloat1622float2(*(__nv_bfloat162*)&r.w); acc[6] += w * f.x; acc[7] += w * f.y;
    }
    #pragma unroll
    for (int i = 0; i < FPL; i++) {
        float v = acc[i] + bias[lane * FPL + i];
        v = (v > 0.f) ? v : (expm1f(v));
        out[(size_t)n * HCn + lane * FPL + i] = v;
    }
}

// ---------------------------------------------------------------------------
// Layer-3 aggregation (H=1) fused with mean-pool accumulation. Unrolled x2.
// ---------------------------------------------------------------------------
__global__ void k_aggregate1_pool(const __nv_bfloat16* __restrict__ hw,
                                  const float* __restrict__ alo,
                                  const float* __restrict__ ahi,
                                  const float* __restrict__ bias,
                                  const int* __restrict__ batch) {
    const int HCn = 64, FPL = 2;
    int warp = (blockIdx.x * blockDim.x + threadIdx.x) >> 5;
    int lane = threadIdx.x & 31;
    if (warp >= NNODES) return;
    int n = warp;
    int beg = g_off[n], deg = g_off[n + 1] - beg;

    float ahin = ahi[n];
    float mx = -1e30f, den = 0.f;
    for (int j = lane; j <= deg; j += 32) {
        int src = (j < deg) ? g_csr[beg + j] : n;
        float e = lrelu(alo[src] + ahin);
        float mn = fmaxf(mx, e);
        den = den * __expf(mx - mn) + __expf(e - mn);
        mx = mn;
    }
    #pragma unroll
    for (int off = 16; off > 0; off >>= 1) {
        float mo = __shfl_xor_sync(0xffffffffu, mx, off);
        float doo = __shfl_xor_sync(0xffffffffu, den, off);
        float mn = fmaxf(mx, mo);
        den = den * __expf(mx - mn) + doo * __expf(mo - mn);
        mx = mn;
    }
    float inv_d = 1.f / (den + 1e-16f);

    float a0 = 0.f, a1 = 0.f;
    const int total = deg + 1;
    int j = 0;
    for (; j + 1 < total; j += 2) {
        int s0 = g_csr[beg + j];
        int s1 = (j + 1 < deg) ? g_csr[beg + j + 1] : n;
        unsigned int r0 = *(const unsigned int*)(hw + (size_t)s0 * HCn + lane * FPL);
        unsigned int r1 = *(const unsigned int*)(hw + (size_t)s1 * HCn + lane * FPL);
        float w0 = __expf(lrelu(alo[s0] + ahin) - mx) * inv_d;
        float w1 = __expf(lrelu(alo[s1] + ahin) - mx) * inv_d;
        float2 f0 = __bfloat1622float2(*(__nv_bfloat162*)&r0);
        float2 f1 = __bfloat1622float2(*(__nv_bfloat162*)&r1);
        a0 += w0 * f0.x + w1 * f1.x;
        a1 += w0 * f0.y + w1 * f1.y;
    }
    if (j < total) {
        int s = (j < deg) ? g_csr[beg + j] : n;
        unsigned int r = *(const unsigned int*)(hw + (size_t)s * HCn + lane * FPL);
        float w = __expf(lrelu(alo[s] + ahin) - mx) * inv_d;
        float2 f = __bfloat1622float2(*(__nv_bfloat162*)&r);
        a0 += w * f.x; a1 += w * f.y;
    }
    float v0 = a0 + bias[lane * FPL];
    float v1 = a1 + bias[lane * FPL + 1];
    v0 = (v0 > 0.f) ? v0 : expm1f(v0);
    v1 = (v1 > 0.f) ? v1 : expm1f(v1);

    int b = batch[n];
    atomicAdd(&g_pool[b * HIDDEN + lane * FPL], v0);
    atomicAdd(&g_pool[b * HIDDEN + lane * FPL + 1], v1);
    if (lane == 0) atomicAdd(&g_cnt[b], 1.f);
}

// ---------------------------------------------------------------------------
// Heads MLP: one warp per graph
// ---------------------------------------------------------------------------
__global__ void k_mlp(const float* __restrict__ Wc1, const float* __restrict__ bc1,
                      const float* __restrict__ Wc2, const float* __restrict__ bc2,
                      const float* __restrict__ Wr1, const float* __restrict__ br1,
                      const float* __restrict__ Wr2, const float* __restrict__ br2,
                      float* __restrict__ out) {
    int warp = (blockIdx.x * blockDim.x + threadIdx.x) >> 5;
    int lane = threadIdx.x & 31;
    if (warp >= NGRAPHS) return;
    float inv_cnt = 1.f / fmaxf(g_cnt[warp], 1.f);
    const float* gp = &g_pool[warp * HIDDEN];

    {
        float h0 = bc1[lane], h1 = bc1[lane + 32];
        for (int c = 0; c < HIDDEN; c++) {
            float gc = gp[c] * inv_cnt;
            h0 += Wc1[lane * HIDDEN + c] * gc;
            h1 += Wc1[(lane + 32) * HIDDEN + c] * gc;
        }
        h0 = fmaxf(h0, 0.f); h1 = fmaxf(h1, 0.f);
        float s = Wc2[lane] * h0 + Wc2[lane + 32] * h1;
        #pragma unroll
        for (int off = 16; off > 0; off >>= 1) s += __shfl_xor_sync(0xffffffffu, s, off);
        if (lane == 0) out[warp] = s + bc2[0];
    }
    {
        float h0 = br1[lane], h1 = br1[lane + 32];
        for (int c = 0; c < HIDDEN; c++) {
            float gc = gp[c] * inv_cnt;
            h0 += Wr1[lane * HIDDEN + c] * gc;
            h1 += Wr1[(lane + 32) * HIDDEN + c] * gc;
        }
        h0 = fmaxf(h0, 0.f); h1 = fmaxf(h1, 0.f);
        float s = Wr2[lane] * h0 + Wr2[lane + 32] * h1;
        #pragma unroll
        for (int off = 16; off > 0; off >>= 1) s += __shfl_xor_sync(0xffffffffu, s, off);
        if (lane == 0) out[NGRAPHS + warp] = s + br2[0];
    }
}

// ---------------------------------------------------------------------------
// Launch
// ---------------------------------------------------------------------------
extern "C" void kernel_launch(void* const* d_in, const int* in_sizes, int n_in,
                              void* d_out, int out_size) {
    const float* x     = (const float*)d_in[0];
    const int*   ei    = (const int*)d_in[1];
    const int*   batch = (const int*)d_in[2];
    const float* W1  = (const float*)d_in[3];
    const float* as1 = (const float*)d_in[4];
    const float* ad1 = (const float*)d_in[5];
    const float* b1  = (const float*)d_in[6];
    const float* W2  = (const float*)d_in[7];
    const float* as2 = (const float*)d_in[8];
    const float* ad2 = (const float*)d_in[9];
    const float* b2  = (const float*)d_in[10];
    const float* W3  = (const float*)d_in[11];
    const float* as3 = (const float*)d_in[12];
    const float* ad3 = (const float*)d_in[13];
    const float* b3  = (const float*)d_in[14];
    const float* Wc1 = (const float*)d_in[15];
    const float* bc1 = (const float*)d_in[16];
    const float* Wc2 = (const float*)d_in[17];
    const float* bc2 = (const float*)d_in[18];
    const float* Wr1 = (const float*)d_in[19];
    const float* br1 = (const float*)d_in[20];
    const float* Wr2 = (const float*)d_in[21];
    const float* br2 = (const float*)d_in[22];
    float* out = (float*)d_out;

    const int* srcp = ei;
    const int* dstp = ei + NEDGES;

    k_zero_csr<<<(NNODES + 256) / 256, 256>>>();
    k_hist<<<(NEDGES + 255) / 256, 256>>>(dstp);
    k_scan<<<1, 1024>>>();
    k_scatter<<<(NEDGES + 255) / 256, 256>>>(srcp, dstp);

    __nv_bfloat16* hw_p = nullptr; cudaGetSymbolAddress((void**)&hw_p, g_hw);
    float* feat_p = nullptr; cudaGetSymbolAddress((void**)&feat_p, g_feat);
    float* alo_p  = nullptr; cudaGetSymbolAddress((void**)&alo_p,  g_alo);
    float* ahi_p  = nullptr; cudaGetSymbolAddress((void**)&ahi_p,  g_ahi);

    const int warps_grid = (NNODES * 32 + 255) / 256;
    const int mblocks = (NNODES + GBM - 1) / GBM;

    // Layer 1
    {
        dim3 grid(HC1 / GBN, mblocks);
        k_gemm_bf16<<<grid, 256>>>(x, W1, hw_p, NNODES, HC1, IN_DIM, as1, ad1, alo_p, ahi_p, HEADS);
        k_aggregate4<<<warps_grid, 256>>>(hw_p, alo_p, ahi_p, b1, feat_p);
    }
    // Layer 2
    {
        dim3 grid(HC1 / GBN, mblocks);
        k_gemm_bf16<<<grid, 256>>>(feat_p, W2, hw_p, NNODES, HC1, HC1, as2, ad2, alo_p, ahi_p, HEADS);
        k_aggregate4<<<warps_grid, 256>>>(hw_p, alo_p, ahi_p, b2, feat_p);
    }
    // Layer 3 (heads=1) fused with pool
    {
        dim3 grid(HIDDEN / GBN, mblocks);
        k_gemm_bf16<<<grid, 256>>>(feat_p, W3, hw_p, NNODES, HIDDEN, HC1, as3, ad3, alo_p, ahi_p, 1);
        k_aggregate1_pool<<<warps_grid, 256>>>(hw_p, alo_p, ahi_p, b3, batch);
    }

    k_mlp<<<(NGRAPHS * 32 + 255) / 256, 256>>>(Wc1, bc1, Wc2, bc2, Wr1, br1, Wr2, br2, out);
}